// round 5
// baseline (speedup 1.0000x reference)
#include <cuda_runtime.h>
#include <cuda_bf16.h>
#include <math.h>

// ---------------------------------------------------------------------------
// Model constants
// ---------------------------------------------------------------------------
#define TT   2048      // sequence length
#define HH   2048      // hidden
#define NHD  8         // num q heads
#define NKV_ 2         // num kv heads
#define DD   256       // head dim
#define II   8192      // mlp intermediate
#define GG   4         // NH / NKV
#define WIN_ 512
#define EPS_ 1e-6f

// ---------------------------------------------------------------------------
// Scratch (device globals -- no allocation allowed)
// ---------------------------------------------------------------------------
__device__ float g_h  [TT * HH];
__device__ float g_x  [TT * HH];
__device__ float g_q  [TT * NHD * DD];
__device__ float g_k  [TT * NKV_ * DD];
__device__ float g_v  [TT * NKV_ * DD];
__device__ float g_att[TT * NHD * DD];
__device__ float g_tmp[TT * HH];
__device__ float g_gate[(size_t)TT * II];
__device__ float g_up  [(size_t)TT * II];

// ---------------------------------------------------------------------------
// Block reduction helper (sum)
// ---------------------------------------------------------------------------
__device__ __forceinline__ float block_reduce_sum(float v, float* red) {
    #pragma unroll
    for (int off = 16; off; off >>= 1) v += __shfl_xor_sync(0xffffffffu, v, off);
    int lane = threadIdx.x & 31, wid = threadIdx.x >> 5;
    if (lane == 0) red[wid] = v;
    __syncthreads();
    int nw = (blockDim.x + 31) >> 5;
    if (wid == 0) {
        float s = (threadIdx.x < nw) ? red[threadIdx.x] : 0.f;
        #pragma unroll
        for (int off = 16; off; off >>= 1) s += __shfl_xor_sync(0xffffffffu, s, off);
        if (lane == 0) red[0] = s;
    }
    __syncthreads();
    return red[0];
}

// ---------------------------------------------------------------------------
// Embedding gather * sqrt(H)
// ---------------------------------------------------------------------------
__global__ void embed_kernel(const float* __restrict__ embed,
                             const int* __restrict__ ids,
                             float* __restrict__ h) {
    int t = blockIdx.x;
    int id = ids[t];
    const float* src = embed + (size_t)id * HH;
    float* dst = h + (size_t)t * HH;
    for (int i = threadIdx.x; i < HH; i += blockDim.x)
        dst[i] = src[i] * 45.25483399593904f;   // sqrt(2048)
}

// ---------------------------------------------------------------------------
// RMSNorm: out[row] = x[row] * rsqrt(mean(x^2)+eps) * (w ? w : 1)
// One block per row.
// ---------------------------------------------------------------------------
__global__ void rms_kernel(const float* __restrict__ x,
                           const float* __restrict__ w,
                           float* __restrict__ out, int cols) {
    __shared__ float red[32];
    size_t base = (size_t)blockIdx.x * cols;
    float ss = 0.f;
    for (int i = threadIdx.x; i < cols; i += blockDim.x) {
        float v = x[base + i];
        ss += v * v;
    }
    ss = block_reduce_sum(ss, red);
    float inv = rsqrtf(ss / (float)cols + EPS_);
    for (int i = threadIdx.x; i < cols; i += blockDim.x) {
        float v = x[base + i] * inv;
        if (w) v *= w[i];
        out[base + i] = v;
    }
}

// h[row] += rms(x[row]) * w
__global__ void add_rms_kernel(float* __restrict__ h,
                               const float* __restrict__ x,
                               const float* __restrict__ w, int cols) {
    __shared__ float red[32];
    size_t base = (size_t)blockIdx.x * cols;
    float ss = 0.f;
    for (int i = threadIdx.x; i < cols; i += blockDim.x) {
        float v = x[base + i];
        ss += v * v;
    }
    ss = block_reduce_sum(ss, red);
    float inv = rsqrtf(ss / (float)cols + EPS_);
    for (int i = threadIdx.x; i < cols; i += blockDim.x)
        h[base + i] += x[base + i] * inv * w[i];
}

// ---------------------------------------------------------------------------
// Per-head RMSNorm + RoPE (half-rotation). grid (T, nheads), block = D = 256.
// ---------------------------------------------------------------------------
__global__ void rope_norm_kernel(float* __restrict__ x,
                                 const float* __restrict__ nw,
                                 int nheads, float theta) {
    __shared__ float red[32];
    __shared__ float sn[DD];
    int t = blockIdx.x, hd = blockIdx.y, d = threadIdx.x;
    size_t base = ((size_t)t * nheads + hd) * DD;
    float v = x[base + d];
    float ss = block_reduce_sum(v * v, red);
    float n = v * rsqrtf(ss * (1.f / (float)DD) + EPS_) * nw[d];
    sn[d] = n;
    int j = d & 127;
    // inv freq computed in double, rounded to fp32 (matches XLA to ~1 ulp),
    // angle = fp32(t) * fp32(inv) exactly as reference, trig of that fp32 value.
    float invf = (float)exp(-((double)j / 128.0) * log((double)theta));
    float ang = (float)t * invf;
    float c = (float)cos((double)ang);
    float s = (float)sin((double)ang);
    __syncthreads();
    float other = (d < 128) ? -sn[d + 128] : sn[d - 128];
    x[base + d] = n * c + other * s;
}

// ---------------------------------------------------------------------------
// Attention (online softmax, one block per (query t, head)). 256 threads.
// No 1/sqrt(D) scaling (reference has none). win>0 => sliding window.
// ---------------------------------------------------------------------------
__global__ void attn_kernel(const float* __restrict__ q,
                            const float* __restrict__ k,
                            const float* __restrict__ v,
                            float* __restrict__ o, int win) {
    int t = blockIdx.x, hh = blockIdx.y;
    int kv = hh >> 2;                 // hh / G, G = 4
    int tid = threadIdx.x, lane = tid & 31, w = tid >> 5;
    __shared__ float sq[DD];
    __shared__ float sacc[DD];
    __shared__ float sp[8];
    sq[tid]   = q[((size_t)t * NHD + hh) * DD + tid];
    sacc[tid] = 0.f;
    __syncthreads();

    float m = -3.4e38f, l = 0.f;
    int slo = 0;
    if (win > 0) { slo = t - win + 1; if (slo < 0) slo = 0; }

    for (int s0 = slo; s0 <= t; s0 += 8) {
        int s = s0 + w;
        float sc = -3.4e38f;
        if (s <= t) {
            const float* kr = k + ((size_t)s * NKV_ + kv) * DD;
            float d = 0.f;
            #pragma unroll
            for (int j = 0; j < 8; j++)
                d = fmaf(sq[lane + 32 * j], kr[lane + 32 * j], d);
            #pragma unroll
            for (int off = 16; off; off >>= 1)
                d += __shfl_xor_sync(0xffffffffu, d, off);
            sc = d;
        }
        if (lane == 0) sp[w] = sc;
        __syncthreads();

        float mn = m;
        #pragma unroll
        for (int j = 0; j < 8; j++) mn = fmaxf(mn, sp[j]);
        float scale = expf(m - mn);
        float p[8]; float psum = 0.f;
        #pragma unroll
        for (int j = 0; j < 8; j++) {
            float pj = (s0 + j <= t) ? expf(sp[j] - mn) : 0.f;
            p[j] = pj; psum += pj;
        }
        l = l * scale + psum;
        float a = sacc[tid] * scale;
        #pragma unroll
        for (int j = 0; j < 8; j++) {
            if (s0 + j <= t) {
                const float* vr = v + ((size_t)(s0 + j) * NKV_ + kv) * DD;
                a = fmaf(p[j], vr[tid], a);
            }
        }
        sacc[tid] = a;
        m = mn;
        __syncthreads();
    }
    o[((size_t)t * NHD + hh) * DD + tid] = sacc[tid] / l;
}

// ---------------------------------------------------------------------------
// gelu(tanh approx)(gate) * up  -> gate
// ---------------------------------------------------------------------------
__global__ void gelu_mul_kernel(float* __restrict__ g,
                                const float* __restrict__ u, size_t n) {
    size_t i = (size_t)blockIdx.x * blockDim.x + threadIdx.x;
    if (i < n) {
        float x = g[i];
        float tt = tanhf(0.7978845608028654f * (x + 0.044715f * x * x * x));
        g[i] = 0.5f * x * (1.f + tt) * u[i];
    }
}

// ---------------------------------------------------------------------------
// SGEMM (NT): C[M,N] = A[M,K] * B[N,K]^T   (all fp32, row-major)
// All dims are multiples of tile sizes for this problem -> no bounds checks.
// ---------------------------------------------------------------------------
template <int BM, int BN, int TM, int TN>
__global__ __launch_bounds__(256)
void sgemm_nt(const float* __restrict__ A, const float* __restrict__ B,
              float* __restrict__ C, int M, int N, int K) {
    constexpr int BK = 16;
    constexpr int NT = (BM / TM) * (BN / TN);   // 256
    constexpr int NX = BN / TN;
    constexpr int APT = BM * BK / 4 / NT;       // float4 per thread (A)
    constexpr int BPT = BN * BK / 4 / NT;       // float4 per thread (B)

    __shared__ float As[BK][BM];
    __shared__ float Bs[BK][BN];

    int tid = threadIdx.x;
    int bm = blockIdx.y * BM;
    int bn = blockIdx.x * BN;
    int tx = tid % NX, ty = tid / NX;

    float acc[TM][TN];
    #pragma unroll
    for (int i = 0; i < TM; i++)
        #pragma unroll
        for (int j = 0; j < TN; j++) acc[i][j] = 0.f;

    for (int k0 = 0; k0 < K; k0 += BK) {
        float4 areg[APT], breg[BPT];
        #pragma unroll
        for (int it = 0; it < APT; it++) {
            int idx = tid + it * NT;
            int r = idx >> 2, c = (idx & 3) << 2;
            areg[it] = *(const float4*)(A + (size_t)(bm + r) * K + k0 + c);
        }
        #pragma unroll
        for (int it = 0; it < BPT; it++) {
            int idx = tid + it * NT;
            int r = idx >> 2, c = (idx & 3) << 2;
            breg[it] = *(const float4*)(B + (size_t)(bn + r) * K + k0 + c);
        }
        __syncthreads();
        #pragma unroll
        for (int it = 0; it < APT; it++) {
            int idx = tid + it * NT;
            int r = idx >> 2, c = (idx & 3) << 2;
            As[c + 0][r] = areg[it].x; As[c + 1][r] = areg[it].y;
            As[c + 2][r] = areg[it].z; As[c + 3][r] = areg[it].w;
        }
        #pragma unroll
        for (int it = 0; it < BPT; it++) {
            int idx = tid + it * NT;
            int r = idx >> 2, c = (idx & 3) << 2;
            Bs[c + 0][r] = breg[it].x; Bs[c + 1][r] = breg[it].y;
            Bs[c + 2][r] = breg[it].z; Bs[c + 3][r] = breg[it].w;
        }
        __syncthreads();
        #pragma unroll
        for (int kk = 0; kk < BK; kk++) {
            float ar[TM], br[TN];
            #pragma unroll
            for (int i = 0; i < TM; i++) ar[i] = As[kk][ty * TM + i];
            #pragma unroll
            for (int j = 0; j < TN; j++) br[j] = Bs[kk][tx * TN + j];
            #pragma unroll
            for (int i = 0; i < TM; i++)
                #pragma unroll
                for (int j = 0; j < TN; j++)
                    acc[i][j] = fmaf(ar[i], br[j], acc[i][j]);
        }
    }

    #pragma unroll
    for (int i = 0; i < TM; i++) {
        size_t row = (size_t)(bm + ty * TM + i);
        #pragma unroll
        for (int j = 0; j < TN; j++)
            C[row * N + bn + tx * TN + j] = acc[i][j];
    }
}

// ---------------------------------------------------------------------------
// Host orchestration
// ---------------------------------------------------------------------------
extern "C" void kernel_launch(void* const* d_in, const int* in_sizes, int n_in,
                              void* d_out, int out_size) {
    const float* embed  = (const float*)d_in[0];
    const float* q_w    = (const float*)d_in[1];
    const float* k_w    = (const float*)d_in[2];
    const float* v_w    = (const float*)d_in[3];
    const float* o_w    = (const float*)d_in[4];
    const float* q_norm = (const float*)d_in[5];
    const float* k_norm = (const float*)d_in[6];
    const float* ln1    = (const float*)d_in[7];
    const float* ln2    = (const float*)d_in[8];
    const float* ln3    = (const float*)d_in[9];
    const float* ln4    = (const float*)d_in[10];
    const float* gate_w = (const float*)d_in[11];
    const float* up_w   = (const float*)d_in[12];
    const float* down_w = (const float*)d_in[13];
    const float* fnorm  = (const float*)d_in[14];
    const int*   ids    = (const int*)d_in[15];

    float *h, *x, *q, *k, *v, *att, *tmp, *gate, *up;
    cudaGetSymbolAddress((void**)&h,    g_h);
    cudaGetSymbolAddress((void**)&x,    g_x);
    cudaGetSymbolAddress((void**)&q,    g_q);
    cudaGetSymbolAddress((void**)&k,    g_k);
    cudaGetSymbolAddress((void**)&v,    g_v);
    cudaGetSymbolAddress((void**)&att,  g_att);
    cudaGetSymbolAddress((void**)&tmp,  g_tmp);
    cudaGetSymbolAddress((void**)&gate, g_gate);
    cudaGetSymbolAddress((void**)&up,   g_up);

    embed_kernel<<<TT, 256>>>(embed, ids, h);

    for (int l = 0; l < 4; l++) {
        bool sliding = (l % 2 == 0);            // layers 0,2 sliding; 1,3 full
        float theta  = sliding ? 10000.0f : 1000000.0f;
        int   win    = sliding ? WIN_ : 0;

        // x = rms(h, ln1)
        rms_kernel<<<TT, 256>>>(h, ln1 + (size_t)l * HH, x, HH);

        // q/k/v projections
        sgemm_nt<128, 128, 8, 8><<<dim3(16, 16), 256>>>(
            x, q_w + (size_t)l * NHD * DD * HH, q, TT, NHD * DD, HH);
        sgemm_nt<64, 64, 4, 4><<<dim3(8, 32), 256>>>(
            x, k_w + (size_t)l * NKV_ * DD * HH, k, TT, NKV_ * DD, HH);
        sgemm_nt<64, 64, 4, 4><<<dim3(8, 32), 256>>>(
            x, v_w + (size_t)l * NKV_ * DD * HH, v, TT, NKV_ * DD, HH);

        // per-head norm + rope (q,k); v rms_noscale
        rope_norm_kernel<<<dim3(TT, NHD), 256>>>(q, q_norm + (size_t)l * DD, NHD, theta);
        rope_norm_kernel<<<dim3(TT, NKV_), 256>>>(k, k_norm + (size_t)l * DD, NKV_, theta);
        rms_kernel<<<TT * NKV_, 256>>>(v, nullptr, v, DD);

        // attention
        attn_kernel<<<dim3(TT, NHD), 256>>>(q, k, v, att, win);

        // output projection + residual rms add
        sgemm_nt<128, 128, 8, 8><<<dim3(16, 16), 256>>>(
            att, o_w + (size_t)l * HH * NHD * DD, tmp, TT, HH, NHD * DD);
        add_rms_kernel<<<TT, 256>>>(h, tmp, ln2 + (size_t)l * HH, HH);

        // MLP
        rms_kernel<<<TT, 256>>>(h, ln3 + (size_t)l * HH, x, HH);
        sgemm_nt<128, 128, 8, 8><<<dim3(64, 16), 256>>>(
            x, gate_w + (size_t)l * II * HH, gate, TT, II, HH);
        sgemm_nt<128, 128, 8, 8><<<dim3(64, 16), 256>>>(
            x, up_w + (size_t)l * II * HH, up, TT, II, HH);
        gelu_mul_kernel<<<(unsigned)(((size_t)TT * II + 255) / 256), 256>>>(
            gate, up, (size_t)TT * II);
        sgemm_nt<128, 128, 8, 8><<<dim3(16, 16), 256>>>(
            gate, down_w + (size_t)l * HH * II, tmp, TT, HH, II);
        add_rms_kernel<<<TT, 256>>>(h, tmp, ln4 + (size_t)l * HH, HH);
    }

    // final norm -> output (fp32)
    rms_kernel<<<TT, 256>>>(h, fnorm, (float*)d_out, HH);
}

// round 8
// speedup vs baseline: 1.4611x; 1.4611x over previous
#include <cuda_runtime.h>
#include <cuda_bf16.h>
#include <math.h>
#include <stdint.h>

// ---------------------------------------------------------------------------
// Model constants
// ---------------------------------------------------------------------------
#define TT   2048
#define HH   2048
#define NHD  8
#define NKV_ 2
#define DD   256
#define II   8192
#define L_   4
#define WIN_ 512
#define EPS_ 1e-6f

// ---------------------------------------------------------------------------
// fp32 scratch
// ---------------------------------------------------------------------------
__device__ float g_h  [TT * HH];
__device__ float g_x  [TT * HH];
__device__ float g_q  [TT * NHD * DD];
__device__ float g_k  [TT * NKV_ * DD];
__device__ float g_v  [TT * NKV_ * DD];
__device__ float g_att[TT * NHD * DD];
__device__ float g_tmp[TT * HH];
__device__ float g_gate[(size_t)TT * II];
__device__ float g_up  [(size_t)TT * II];

// bf16 split (hi/lo) weights, all layers
__device__ __nv_bfloat16 g_qw_h[(size_t)L_*HH*HH],        g_qw_l[(size_t)L_*HH*HH];
__device__ __nv_bfloat16 g_kw_h[(size_t)L_*NKV_*DD*HH],   g_kw_l[(size_t)L_*NKV_*DD*HH];
__device__ __nv_bfloat16 g_vw_h[(size_t)L_*NKV_*DD*HH],   g_vw_l[(size_t)L_*NKV_*DD*HH];
__device__ __nv_bfloat16 g_ow_h[(size_t)L_*HH*HH],        g_ow_l[(size_t)L_*HH*HH];
__device__ __nv_bfloat16 g_gw_h[(size_t)L_*II*HH],        g_gw_l[(size_t)L_*II*HH];
__device__ __nv_bfloat16 g_uw_h[(size_t)L_*II*HH],        g_uw_l[(size_t)L_*II*HH];
__device__ __nv_bfloat16 g_dw_h[(size_t)L_*HH*II],        g_dw_l[(size_t)L_*HH*II];
// bf16 split activations
__device__ __nv_bfloat16 g_xa_h[TT*HH],           g_xa_l[TT*HH];
__device__ __nv_bfloat16 g_ga_h[(size_t)TT*II],   g_ga_l[(size_t)TT*II];

// ---------------------------------------------------------------------------
// helpers
// ---------------------------------------------------------------------------
__device__ __forceinline__ uint32_t smem_u32(const void* p) {
    uint32_t a;
    asm("{ .reg .u64 t; cvta.to.shared.u64 t, %1; cvt.u32.u64 %0, t; }" : "=r"(a) : "l"(p));
    return a;
}
__device__ __forceinline__ void cp16(uint32_t dst, const void* src) {
    asm volatile("cp.async.cg.shared.global [%0], [%1], 16;" :: "r"(dst), "l"(src));
}
__device__ __forceinline__ void cp_commit() { asm volatile("cp.async.commit_group;"); }
template<int N> __device__ __forceinline__ void cp_wait() {
    asm volatile("cp.async.wait_group %0;" :: "n"(N));
}
__device__ __forceinline__ void ldsm4(uint32_t* r, uint32_t a) {
    asm volatile("ldmatrix.sync.aligned.m8n8.x4.shared.b16 {%0,%1,%2,%3}, [%4];"
        : "=r"(r[0]), "=r"(r[1]), "=r"(r[2]), "=r"(r[3]) : "r"(a));
}
__device__ __forceinline__ void mma_bf16(float* d, const uint32_t* a, const uint32_t* b) {
    asm volatile("mma.sync.aligned.m16n8k16.row.col.f32.bf16.bf16.f32 "
        "{%0,%1,%2,%3}, {%4,%5,%6,%7}, {%8,%9}, {%0,%1,%2,%3};"
        : "+f"(d[0]), "+f"(d[1]), "+f"(d[2]), "+f"(d[3])
        : "r"(a[0]), "r"(a[1]), "r"(a[2]), "r"(a[3]), "r"(b[0]), "r"(b[1]));
}

// ---------------------------------------------------------------------------
// fp32 -> (hi,lo) bf16 split
// ---------------------------------------------------------------------------
__global__ void split4_kernel(const float4* __restrict__ x,
                              __nv_bfloat162* __restrict__ hi,
                              __nv_bfloat162* __restrict__ lo, size_t n4) {
    size_t i = (size_t)blockIdx.x * blockDim.x + threadIdx.x;
    if (i >= n4) return;
    float4 v = x[i];
    __nv_bfloat16 h0 = __float2bfloat16(v.x), h1 = __float2bfloat16(v.y);
    __nv_bfloat16 h2 = __float2bfloat16(v.z), h3 = __float2bfloat16(v.w);
    __nv_bfloat16 l0 = __float2bfloat16(v.x - __bfloat162float(h0));
    __nv_bfloat16 l1 = __float2bfloat16(v.y - __bfloat162float(h1));
    __nv_bfloat16 l2 = __float2bfloat16(v.z - __bfloat162float(h2));
    __nv_bfloat16 l3 = __float2bfloat16(v.w - __bfloat162float(h3));
    hi[2*i]   = __nv_bfloat162(h0, h1);
    hi[2*i+1] = __nv_bfloat162(h2, h3);
    lo[2*i]   = __nv_bfloat162(l0, l1);
    lo[2*i+1] = __nv_bfloat162(l2, l3);
}

// ---------------------------------------------------------------------------
// mma.sync bf16-split NT GEMM:  C[M,N] = A[M,K] * B[N,K]^T  (fp32 accuracy)
// 128x128 CTA tile, BK=32, 8 warps (2x4, 64x32 warp tiles), double-buffered.
// ---------------------------------------------------------------------------
#define BK_       32
#define STRIDE_E  40                        // bf16 elems per smem row (padded)
#define ROW_B     (STRIDE_E * 2)            // 80 bytes per row
#define MAT_B     (128 * ROW_B)             // 10240 bytes per matrix tile
#define STAGE_B   (4 * MAT_B)               // Ah, Al, Bh, Bl
#define GEMM_SMEM (2 * STAGE_B)             // 81920

__device__ __forceinline__ void gemm_load_stage(
    const __nv_bfloat16* __restrict__ Ah, const __nv_bfloat16* __restrict__ Al,
    const __nv_bfloat16* __restrict__ Bh, const __nv_bfloat16* __restrict__ Bl,
    int K, int bm, int bn, int k0, uint32_t sb, int tid)
{
    #pragma unroll
    for (int i = 0; i < 2; i++) {
        int idx = tid + (i << 8);       // 0..511
        int r = idx >> 2;               // row 0..127
        int c = idx & 3;                // 16B chunk 0..3
        size_t ga = (size_t)(bm + r) * K + k0 + c * 8;
        size_t gb = (size_t)(bn + r) * K + k0 + c * 8;
        uint32_t so = r * ROW_B + c * 16;
        cp16(sb             + so, Ah + ga);
        cp16(sb +   MAT_B   + so, Al + ga);
        cp16(sb + 2*MAT_B   + so, Bh + gb);
        cp16(sb + 3*MAT_B   + so, Bl + gb);
    }
    cp_commit();
}

__global__ __launch_bounds__(256)
void gemm_mma(const __nv_bfloat16* __restrict__ Ah, const __nv_bfloat16* __restrict__ Al,
              const __nv_bfloat16* __restrict__ Bh, const __nv_bfloat16* __restrict__ Bl,
              float* __restrict__ C, int M, int N, int K)
{
    extern __shared__ char dsm[];
    uint32_t sbase = smem_u32(dsm);
    int tid  = threadIdx.x;
    int lane = tid & 31, w = tid >> 5;
    int wm = w >> 2, wn = w & 3;        // warp grid 2 x 4
    int bm = blockIdx.y * 128, bn = blockIdx.x * 128;

    float acc[4][4][4];
    #pragma unroll
    for (int i = 0; i < 4; i++)
        #pragma unroll
        for (int j = 0; j < 4; j++)
            #pragma unroll
            for (int q = 0; q < 4; q++) acc[i][j][q] = 0.f;

    int lrow = lane & 15;
    int lkb  = (lane >> 4) << 4;        // 0 or 16 bytes

    int nch = K / BK_;
    gemm_load_stage(Ah, Al, Bh, Bl, K, bm, bn, 0, sbase, tid);

    for (int c = 0; c < nch; c++) {
        uint32_t sb = sbase + (c & 1) * STAGE_B;
        if (c + 1 < nch) {
            gemm_load_stage(Ah, Al, Bh, Bl, K, bm, bn, (c + 1) * BK_,
                            sbase + ((c + 1) & 1) * STAGE_B, tid);
            cp_wait<1>();
        } else {
            cp_wait<0>();
        }
        __syncthreads();

        #pragma unroll
        for (int ks = 0; ks < 2; ks++) {
            uint32_t abase = sb + (wm * 64 + lrow) * ROW_B + ks * 32 + lkb;
            uint32_t ah[4][4], al[4][4];
            #pragma unroll
            for (int mt = 0; mt < 4; mt++) {
                ldsm4(ah[mt], abase + mt * 16 * ROW_B);
                ldsm4(al[mt], abase + MAT_B + mt * 16 * ROW_B);
            }
            uint32_t bh[4][2], bl[4][2];
            #pragma unroll
            for (int np = 0; np < 2; np++) {
                uint32_t bbase = sb + 2 * MAT_B +
                                 (wn * 32 + np * 16 + lrow) * ROW_B + ks * 32 + lkb;
                uint32_t r[4];
                ldsm4(r, bbase);
                bh[np*2][0]   = r[0]; bh[np*2][1]   = r[2];
                bh[np*2+1][0] = r[1]; bh[np*2+1][1] = r[3];
                ldsm4(r, bbase + MAT_B);
                bl[np*2][0]   = r[0]; bl[np*2][1]   = r[2];
                bl[np*2+1][0] = r[1]; bl[np*2+1][1] = r[3];
            }
            #pragma unroll
            for (int mt = 0; mt < 4; mt++)
                #pragma unroll
                for (int nt = 0; nt < 4; nt++) {
                    mma_bf16(acc[mt][nt], ah[mt], bh[nt]);
                    mma_bf16(acc[mt][nt], ah[mt], bl[nt]);
                    mma_bf16(acc[mt][nt], al[mt], bh[nt]);
                }
        }
        __syncthreads();
    }

    // epilogue: fragment -> gmem (float2 stores)
    #pragma unroll
    for (int mt = 0; mt < 4; mt++) {
        int row0 = bm + wm * 64 + mt * 16 + (lane >> 2);
        #pragma unroll
        for (int nt = 0; nt < 4; nt++) {
            int col = bn + wn * 32 + nt * 8 + (lane & 3) * 2;
            *(float2*)&C[(size_t)row0 * N + col] =
                make_float2(acc[mt][nt][0], acc[mt][nt][1]);
            *(float2*)&C[(size_t)(row0 + 8) * N + col] =
                make_float2(acc[mt][nt][2], acc[mt][nt][3]);
        }
    }
}

// ---------------------------------------------------------------------------
// elementwise / norm / attention kernels
// ---------------------------------------------------------------------------
__device__ __forceinline__ float block_reduce_sum(float v, float* red) {
    #pragma unroll
    for (int off = 16; off; off >>= 1) v += __shfl_xor_sync(0xffffffffu, v, off);
    int lane = threadIdx.x & 31, wid = threadIdx.x >> 5;
    if (lane == 0) red[wid] = v;
    __syncthreads();
    int nw = (blockDim.x + 31) >> 5;
    if (wid == 0) {
        float s = (threadIdx.x < nw) ? red[threadIdx.x] : 0.f;
        #pragma unroll
        for (int off = 16; off; off >>= 1) s += __shfl_xor_sync(0xffffffffu, s, off);
        if (lane == 0) red[0] = s;
    }
    __syncthreads();
    return red[0];
}

__global__ void embed_kernel(const float* __restrict__ embed,
                             const int* __restrict__ ids, float* __restrict__ h) {
    int t = blockIdx.x;
    const float* src = embed + (size_t)ids[t] * HH;
    float* dst = h + (size_t)t * HH;
    for (int i = threadIdx.x; i < HH; i += blockDim.x)
        dst[i] = src[i] * 45.25483399593904f;
}

__global__ void rms_kernel(const float* __restrict__ x, const float* __restrict__ w,
                           float* __restrict__ out, int cols) {
    __shared__ float red[32];
    size_t base = (size_t)blockIdx.x * cols;
    float ss = 0.f;
    for (int i = threadIdx.x; i < cols; i += blockDim.x) { float v = x[base+i]; ss += v*v; }
    ss = block_reduce_sum(ss, red);
    float inv = rsqrtf(ss / (float)cols + EPS_);
    for (int i = threadIdx.x; i < cols; i += blockDim.x) {
        float v = x[base+i] * inv;
        if (w) v *= w[i];
        out[base+i] = v;
    }
}

__global__ void add_rms_kernel(float* __restrict__ h, const float* __restrict__ x,
                               const float* __restrict__ w, int cols) {
    __shared__ float red[32];
    size_t base = (size_t)blockIdx.x * cols;
    float ss = 0.f;
    for (int i = threadIdx.x; i < cols; i += blockDim.x) { float v = x[base+i]; ss += v*v; }
    ss = block_reduce_sum(ss, red);
    float inv = rsqrtf(ss / (float)cols + EPS_);
    for (int i = threadIdx.x; i < cols; i += blockDim.x)
        h[base+i] += x[base+i] * inv * w[i];
}

__global__ void rope_norm_kernel(float* __restrict__ x, const float* __restrict__ nw,
                                 int nheads, float theta) {
    __shared__ float red[32];
    __shared__ float sn[DD];
    int t = blockIdx.x, hd = blockIdx.y, d = threadIdx.x;
    size_t base = ((size_t)t * nheads + hd) * DD;
    float v = x[base + d];
    float ss = block_reduce_sum(v * v, red);
    float n = v * rsqrtf(ss * (1.f / (float)DD) + EPS_) * nw[d];
    sn[d] = n;
    int j = d & 127;
    float invf = (float)exp(-((double)j / 128.0) * log((double)theta));
    float ang = (float)t * invf;
    float c = (float)cos((double)ang);
    float s = (float)sin((double)ang);
    __syncthreads();
    float other = (d < 128) ? -sn[d + 128] : sn[d - 128];
    x[base + d] = n * c + other * s;
}

__global__ void attn_kernel(const float* __restrict__ q, const float* __restrict__ k,
                            const float* __restrict__ v, float* __restrict__ o, int win) {
    int t = blockIdx.x, hh = blockIdx.y;
    int kv = hh >> 2;
    int tid = threadIdx.x, lane = tid & 31, w = tid >> 5;
    __shared__ float sq[DD];
    __shared__ float sacc[DD];
    __shared__ float sp[8];
    sq[tid]   = q[((size_t)t * NHD + hh) * DD + tid];
    sacc[tid] = 0.f;
    __syncthreads();

    float m = -3.4e38f, l = 0.f;
    int slo = 0;
    if (win > 0) { slo = t - win + 1; if (slo < 0) slo = 0; }

    for (int s0 = slo; s0 <= t; s0 += 8) {
        int s = s0 + w;
        float sc = -3.4e38f;
        if (s <= t) {
            const float* kr = k + ((size_t)s * NKV_ + kv) * DD;
            float d = 0.f;
            #pragma unroll
            for (int j = 0; j < 8; j++)
                d = fmaf(sq[lane + 32*j], kr[lane + 32*j], d);
            #pragma unroll
            for (int off = 16; off; off >>= 1)
                d += __shfl_xor_sync(0xffffffffu, d, off);
            sc = d;
        }
        if (lane == 0) sp[w] = sc;
        __syncthreads();

        float mn = m;
        #pragma unroll
        for (int j = 0; j < 8; j++) mn = fmaxf(mn, sp[j]);
        float scale = expf(m - mn);
        float p[8]; float psum = 0.f;
        #pragma unroll
        for (int j = 0; j < 8; j++) {
            float pj = (s0 + j <= t) ? expf(sp[j] - mn) : 0.f;
            p[j] = pj; psum += pj;
        }
        l = l * scale + psum;
        float a = sacc[tid] * scale;
        #pragma unroll
        for (int j = 0; j < 8; j++) {
            if (s0 + j <= t) {
                const float* vr = v + ((size_t)(s0 + j) * NKV_ + kv) * DD;
                a = fmaf(p[j], vr[tid], a);
            }
        }
        sacc[tid] = a;
        m = mn;
        __syncthreads();
    }
    o[((size_t)t * NHD + hh) * DD + tid] = sacc[tid] / l;
}

__global__ void gelu_mul_kernel(float* __restrict__ g, const float* __restrict__ u, size_t n) {
    size_t i = (size_t)blockIdx.x * blockDim.x + threadIdx.x;
    if (i < n) {
        float x = g[i];
        float tt = tanhf(0.7978845608028654f * (x + 0.044715f * x * x * x));
        g[i] = 0.5f * x * (1.f + tt) * u[i];
    }
}

// ---------------------------------------------------------------------------
// Host orchestration
// ---------------------------------------------------------------------------
static void split_launch(const float* src, __nv_bfloat16* hi, __nv_bfloat16* lo, size_t n) {
    size_t n4 = n >> 2;
    unsigned grid = (unsigned)((n4 + 255) / 256);
    split4_kernel<<<grid, 256>>>((const float4*)src, (__nv_bfloat162*)hi,
                                 (__nv_bfloat162*)lo, n4);
}

extern "C" void kernel_launch(void* const* d_in, const int* in_sizes, int n_in,
                              void* d_out, int out_size) {
    const float* embed  = (const float*)d_in[0];
    const float* q_w    = (const float*)d_in[1];
    const float* k_w    = (const float*)d_in[2];
    const float* v_w    = (const float*)d_in[3];
    const float* o_w    = (const float*)d_in[4];
    const float* q_norm = (const float*)d_in[5];
    const float* k_norm = (const float*)d_in[6];
    const float* ln1    = (const float*)d_in[7];
    const float* ln2    = (const float*)d_in[8];
    const float* ln3    = (const float*)d_in[9];
    const float* ln4    = (const float*)d_in[10];
    const float* gate_w = (const float*)d_in[11];
    const float* up_w   = (const float*)d_in[12];
    const float* down_w = (const float*)d_in[13];
    const float* fnorm  = (const float*)d_in[14];
    const int*   ids    = (const int*)d_in[15];

    float *h, *x, *q, *k, *v, *att, *tmp, *gate, *up;
    cudaGetSymbolAddress((void**)&h,    g_h);
    cudaGetSymbolAddress((void**)&x,    g_x);
    cudaGetSymbolAddress((void**)&q,    g_q);
    cudaGetSymbolAddress((void**)&k,    g_k);
    cudaGetSymbolAddress((void**)&v,    g_v);
    cudaGetSymbolAddress((void**)&att,  g_att);
    cudaGetSymbolAddress((void**)&tmp,  g_tmp);
    cudaGetSymbolAddress((void**)&gate, g_gate);
    cudaGetSymbolAddress((void**)&up,   g_up);

    __nv_bfloat16 *qwh,*qwl,*kwh,*kwl,*vwh,*vwl,*owh,*owl,*gwh,*gwl,*uwh,*uwl,*dwh,*dwl;
    __nv_bfloat16 *xah,*xal,*gah,*gal;
    cudaGetSymbolAddress((void**)&qwh, g_qw_h); cudaGetSymbolAddress((void**)&qwl, g_qw_l);
    cudaGetSymbolAddress((void**)&kwh, g_kw_h); cudaGetSymbolAddress((void**)&kwl, g_kw_l);
    cudaGetSymbolAddress((void**)&vwh, g_vw_h); cudaGetSymbolAddress((void**)&vwl, g_vw_l);
    cudaGetSymbolAddress((void**)&owh, g_ow_h); cudaGetSymbolAddress((void**)&owl, g_ow_l);
    cudaGetSymbolAddress((void**)&gwh, g_gw_h); cudaGetSymbolAddress((void**)&gwl, g_gw_l);
    cudaGetSymbolAddress((void**)&uwh, g_uw_h); cudaGetSymbolAddress((void**)&uwl, g_uw_l);
    cudaGetSymbolAddress((void**)&dwh, g_dw_h); cudaGetSymbolAddress((void**)&dwl, g_dw_l);
    cudaGetSymbolAddress((void**)&xah, g_xa_h); cudaGetSymbolAddress((void**)&xal, g_xa_l);
    cudaGetSymbolAddress((void**)&gah, g_ga_h); cudaGetSymbolAddress((void**)&gal, g_ga_l);

    cudaFuncSetAttribute(gemm_mma, cudaFuncAttributeMaxDynamicSharedMemorySize, GEMM_SMEM);

    // weight conversion (all layers)
    split_launch(q_w,    qwh, qwl, (size_t)L_*HH*HH);
    split_launch(k_w,    kwh, kwl, (size_t)L_*NKV_*DD*HH);
    split_launch(v_w,    vwh, vwl, (size_t)L_*NKV_*DD*HH);
    split_launch(o_w,    owh, owl, (size_t)L_*HH*HH);
    split_launch(gate_w, gwh, gwl, (size_t)L_*II*HH);
    split_launch(up_w,   uwh, uwl, (size_t)L_*II*HH);
    split_launch(down_w, dwh, dwl, (size_t)L_*HH*II);

    embed_kernel<<<TT, 256>>>(embed, ids, h);

    auto gemm = [&](const __nv_bfloat16* Ah, const __nv_bfloat16* Al,
                    const __nv_bfloat16* Bh, const __nv_bfloat16* Bl,
                    float* C, int M, int N, int K) {
        dim3 grid(N / 128, M / 128);
        gemm_mma<<<grid, 256, GEMM_SMEM>>>(Ah, Al, Bh, Bl, C, M, N, K);
    };

    for (int l = 0; l < 4; l++) {
        bool sliding = (l % 2 == 0);
        float theta  = sliding ? 10000.0f : 1000000.0f;
        int   win    = sliding ? WIN_ : 0;

        rms_kernel<<<TT, 256>>>(h, ln1 + (size_t)l * HH, x, HH);
        split_launch(x, xah, xal, (size_t)TT * HH);

        gemm(xah, xal, qwh + (size_t)l*HH*HH,      qwl + (size_t)l*HH*HH,      q, TT, HH,      HH);
        gemm(xah, xal, kwh + (size_t)l*NKV_*DD*HH, kwl + (size_t)l*NKV_*DD*HH, k, TT, NKV_*DD, HH);
        gemm(xah, xal, vwh + (size_t)l*NKV_*DD*HH, vwl + (size_t)l*NKV_*DD*HH, v, TT, NKV_*DD, HH);

        rope_norm_kernel<<<dim3(TT, NHD),  256>>>(q, q_norm + (size_t)l * DD, NHD,  theta);
        rope_norm_kernel<<<dim3(TT, NKV_), 256>>>(k, k_norm + (size_t)l * DD, NKV_, theta);
        rms_kernel<<<TT * NKV_, 256>>>(v, nullptr, v, DD);

        attn_kernel<<<dim3(TT, NHD), 256>>>(q, k, v, att, win);

        split_launch(att, xah, xal, (size_t)TT * HH);
        gemm(xah, xal, owh + (size_t)l*HH*HH, owl + (size_t)l*HH*HH, tmp, TT, HH, HH);
        add_rms_kernel<<<TT, 256>>>(h, tmp, ln2 + (size_t)l * HH, HH);

        rms_kernel<<<TT, 256>>>(h, ln3 + (size_t)l * HH, x, HH);
        split_launch(x, xah, xal, (size_t)TT * HH);
        gemm(xah, xal, gwh + (size_t)l*II*HH, gwl + (size_t)l*II*HH, gate, TT, II, HH);
        gemm(xah, xal, uwh + (size_t)l*II*HH, uwl + (size_t)l*II*HH, up,   TT, II, HH);
        gelu_mul_kernel<<<(unsigned)(((size_t)TT*II + 255) / 256), 256>>>(
            gate, up, (size_t)TT * II);
        split_launch(gate, gah, gal, (size_t)TT * II);
        gemm(gah, gal, dwh + (size_t)l*HH*II, dwl + (size_t)l*HH*II, tmp, TT, HH, II);
        add_rms_kernel<<<TT, 256>>>(h, tmp, ln4 + (size_t)l * HH, HH);
    }

    rms_kernel<<<TT, 256>>>(h, fnorm, (float*)d_out, HH);
}

// round 12
// speedup vs baseline: 2.2083x; 1.5114x over previous
#include <cuda_runtime.h>
#include <cuda_bf16.h>
#include <math.h>
#include <stdint.h>

// ---------------------------------------------------------------------------
// Model constants
// ---------------------------------------------------------------------------
#define TT   2048
#define HH   2048
#define NHD  8
#define NKV_ 2
#define DD   256
#define II   8192
#define L_   4
#define WIN_ 512
#define EPS_ 1e-6f

// ---------------------------------------------------------------------------
// fp32 scratch
// ---------------------------------------------------------------------------
__device__ float g_h  [TT * HH];
__device__ float g_q  [TT * NHD * DD];
__device__ float g_k  [TT * NKV_ * DD];
__device__ float g_v  [TT * NKV_ * DD];
__device__ float g_tmp[TT * HH];
__device__ float g_gate[(size_t)TT * II];
__device__ float g_up  [(size_t)TT * II];

// bf16 split (hi/lo) weights, all layers
__device__ __nv_bfloat16 g_qw_h[(size_t)L_*HH*HH],        g_qw_l[(size_t)L_*HH*HH];
__device__ __nv_bfloat16 g_kw_h[(size_t)L_*NKV_*DD*HH],   g_kw_l[(size_t)L_*NKV_*DD*HH];
__device__ __nv_bfloat16 g_vw_h[(size_t)L_*NKV_*DD*HH],   g_vw_l[(size_t)L_*NKV_*DD*HH];
__device__ __nv_bfloat16 g_ow_h[(size_t)L_*HH*HH],        g_ow_l[(size_t)L_*HH*HH];
__device__ __nv_bfloat16 g_gw_h[(size_t)L_*II*HH],        g_gw_l[(size_t)L_*II*HH];
__device__ __nv_bfloat16 g_uw_h[(size_t)L_*II*HH],        g_uw_l[(size_t)L_*II*HH];
__device__ __nv_bfloat16 g_dw_h[(size_t)L_*HH*II],        g_dw_l[(size_t)L_*HH*II];
// bf16 split activations
__device__ __nv_bfloat16 g_xa_h[TT*HH],           g_xa_l[TT*HH];
__device__ __nv_bfloat16 g_ga_h[(size_t)TT*II],   g_ga_l[(size_t)TT*II];

// ---------------------------------------------------------------------------
// helpers
// ---------------------------------------------------------------------------
__device__ __forceinline__ uint32_t smem_u32(const void* p) {
    uint32_t a;
    asm("{ .reg .u64 t; cvta.to.shared.u64 t, %1; cvt.u32.u64 %0, t; }" : "=r"(a) : "l"(p));
    return a;
}
__device__ __forceinline__ void cp16(uint32_t dst, const void* src) {
    asm volatile("cp.async.cg.shared.global [%0], [%1], 16;" :: "r"(dst), "l"(src));
}
__device__ __forceinline__ void cp_commit() { asm volatile("cp.async.commit_group;"); }
template<int N> __device__ __forceinline__ void cp_wait() {
    asm volatile("cp.async.wait_group %0;" :: "n"(N));
}
__device__ __forceinline__ void ldsm4(uint32_t* r, uint32_t a) {
    asm volatile("ldmatrix.sync.aligned.m8n8.x4.shared.b16 {%0,%1,%2,%3}, [%4];"
        : "=r"(r[0]), "=r"(r[1]), "=r"(r[2]), "=r"(r[3]) : "r"(a));
}
__device__ __forceinline__ void mma_bf16(float* d, const uint32_t* a, const uint32_t* b) {
    asm volatile("mma.sync.aligned.m16n8k16.row.col.f32.bf16.bf16.f32 "
        "{%0,%1,%2,%3}, {%4,%5,%6,%7}, {%8,%9}, {%0,%1,%2,%3};"
        : "+f"(d[0]), "+f"(d[1]), "+f"(d[2]), "+f"(d[3])
        : "r"(a[0]), "r"(a[1]), "r"(a[2]), "r"(a[3]), "r"(b[0]), "r"(b[1]));
}
__device__ __forceinline__ void split1(float v, __nv_bfloat16& h, __nv_bfloat16& l) {
    h = __float2bfloat16(v);
    l = __float2bfloat16(v - __bfloat162float(h));
}

// ---------------------------------------------------------------------------
// Fused weight split: one launch for all 7 weight groups
// ---------------------------------------------------------------------------
struct WSplit {
    const float4* src[7];
    __nv_bfloat162* hi[7];
    __nv_bfloat162* lo[7];
    size_t cum[8];              // cumulative float4 counts
};
__global__ void wsplit_kernel(WSplit ws) {
    size_t i = (size_t)blockIdx.x * blockDim.x + threadIdx.x;
    if (i >= ws.cum[7]) return;
    int seg = 0;
    #pragma unroll
    for (int s = 1; s < 7; s++) if (i >= ws.cum[s]) seg = s;
    size_t j = i - ws.cum[seg];
    float4 v = ws.src[seg][j];
    __nv_bfloat16 h0,h1,h2,h3,l0,l1,l2,l3;
    split1(v.x,h0,l0); split1(v.y,h1,l1); split1(v.z,h2,l2); split1(v.w,h3,l3);
    ws.hi[seg][2*j]   = __nv_bfloat162(h0,h1);
    ws.hi[seg][2*j+1] = __nv_bfloat162(h2,h3);
    ws.lo[seg][2*j]   = __nv_bfloat162(l0,l1);
    ws.lo[seg][2*j+1] = __nv_bfloat162(l2,l3);
}

// ---------------------------------------------------------------------------
// mma.sync bf16-split NT GEMM:  C[M,N] = A[M,K] * B[N,K]^T  (fp32 accuracy)
// 128x128 CTA tile, BK=32, 8 warps, double-buffered, 2 CTAs/SM.
// ---------------------------------------------------------------------------
#define BK_       32
#define STRIDE_E  40
#define ROW_B     (STRIDE_E * 2)            // 80 bytes per row
#define MAT_B     (128 * ROW_B)             // 10240 bytes per matrix tile
#define STAGE_B   (4 * MAT_B)
#define GEMM_SMEM (2 * STAGE_B)             // 81920

__device__ __forceinline__ void gemm_load_stage(
    const __nv_bfloat16* __restrict__ Ah, const __nv_bfloat16* __restrict__ Al,
    const __nv_bfloat16* __restrict__ Bh, const __nv_bfloat16* __restrict__ Bl,
    int K, int bm, int bn, int k0, uint32_t sb, int tid)
{
    #pragma unroll
    for (int i = 0; i < 2; i++) {
        int idx = tid + (i << 8);
        int r = idx >> 2;
        int c = idx & 3;
        size_t ga = (size_t)(bm + r) * K + k0 + c * 8;
        size_t gb = (size_t)(bn + r) * K + k0 + c * 8;
        uint32_t so = r * ROW_B + c * 16;
        cp16(sb           + so, Ah + ga);
        cp16(sb +   MAT_B + so, Al + ga);
        cp16(sb + 2*MAT_B + so, Bh + gb);
        cp16(sb + 3*MAT_B + so, Bl + gb);
    }
    cp_commit();
}

__global__ __launch_bounds__(256, 2)
void gemm_mma(const __nv_bfloat16* __restrict__ Ah, const __nv_bfloat16* __restrict__ Al,
              const __nv_bfloat16* __restrict__ Bh, const __nv_bfloat16* __restrict__ Bl,
              float* __restrict__ C, int M, int N, int K)
{
    extern __shared__ char dsm[];
    uint32_t sbase = smem_u32(dsm);
    int tid  = threadIdx.x;
    int lane = tid & 31, w = tid >> 5;
    int wm = w >> 2, wn = w & 3;
    int bm = blockIdx.y * 128, bn = blockIdx.x * 128;

    float acc[4][4][4];
    #pragma unroll
    for (int i = 0; i < 4; i++)
        #pragma unroll
        for (int j = 0; j < 4; j++)
            #pragma unroll
            for (int q = 0; q < 4; q++) acc[i][j][q] = 0.f;

    int lrow = lane & 15;
    int lkb  = (lane >> 4) << 4;

    int nch = K / BK_;
    gemm_load_stage(Ah, Al, Bh, Bl, K, bm, bn, 0, sbase, tid);

    for (int c = 0; c < nch; c++) {
        uint32_t sb = sbase + (c & 1) * STAGE_B;
        if (c + 1 < nch) {
            gemm_load_stage(Ah, Al, Bh, Bl, K, bm, bn, (c + 1) * BK_,
                            sbase + ((c + 1) & 1) * STAGE_B, tid);
            cp_wait<1>();
        } else {
            cp_wait<0>();
        }
        __syncthreads();

        #pragma unroll
        for (int ks = 0; ks < 2; ks++) {
            uint32_t bh[4][2], bl[4][2];
            #pragma unroll
            for (int np = 0; np < 2; np++) {
                uint32_t bbase = sb + 2 * MAT_B +
                                 (wn * 32 + np * 16 + lrow) * ROW_B + ks * 32 + lkb;
                uint32_t r[4];
                ldsm4(r, bbase);
                bh[np*2][0]   = r[0]; bh[np*2][1]   = r[2];
                bh[np*2+1][0] = r[1]; bh[np*2+1][1] = r[3];
                ldsm4(r, bbase + MAT_B);
                bl[np*2][0]   = r[0]; bl[np*2][1]   = r[2];
                bl[np*2+1][0] = r[1]; bl[np*2+1][1] = r[3];
            }
            uint32_t abase = sb + (wm * 64 + lrow) * ROW_B + ks * 32 + lkb;
            #pragma unroll
            for (int mt = 0; mt < 4; mt++) {
                uint32_t ah[4], al[4];
                ldsm4(ah, abase + mt * 16 * ROW_B);
                ldsm4(al, abase + MAT_B + mt * 16 * ROW_B);
                #pragma unroll
                for (int nt = 0; nt < 4; nt++) {
                    mma_bf16(acc[mt][nt], ah, bh[nt]);
                    mma_bf16(acc[mt][nt], ah, bl[nt]);
                    mma_bf16(acc[mt][nt], al, bh[nt]);
                }
            }
        }
        __syncthreads();
    }

    #pragma unroll
    for (int mt = 0; mt < 4; mt++) {
        int row0 = bm + wm * 64 + mt * 16 + (lane >> 2);
        #pragma unroll
        for (int nt = 0; nt < 4; nt++) {
            int col = bn + wn * 32 + nt * 8 + (lane & 3) * 2;
            *(float2*)&C[(size_t)row0 * N + col] =
                make_float2(acc[mt][nt][0], acc[mt][nt][1]);
            *(float2*)&C[(size_t)(row0 + 8) * N + col] =
                make_float2(acc[mt][nt][2], acc[mt][nt][3]);
        }
    }
}

// ---------------------------------------------------------------------------
// norm / elementwise kernels
// ---------------------------------------------------------------------------
__device__ __forceinline__ float block_reduce_sum(float v, float* red) {
    #pragma unroll
    for (int off = 16; off; off >>= 1) v += __shfl_xor_sync(0xffffffffu, v, off);
    int lane = threadIdx.x & 31, wid = threadIdx.x >> 5;
    if (lane == 0) red[wid] = v;
    __syncthreads();
    int nw = (blockDim.x + 31) >> 5;
    if (wid == 0) {
        float s = (threadIdx.x < nw) ? red[threadIdx.x] : 0.f;
        #pragma unroll
        for (int off = 16; off; off >>= 1) s += __shfl_xor_sync(0xffffffffu, s, off);
        if (lane == 0) red[0] = s;
    }
    __syncthreads();
    return red[0];
}

__global__ void embed_kernel(const float* __restrict__ embed,
                             const int* __restrict__ ids, float* __restrict__ h) {
    int t = blockIdx.x;
    const float* src = embed + (size_t)ids[t] * HH;
    float* dst = h + (size_t)t * HH;
    for (int i = threadIdx.x; i < HH; i += blockDim.x)
        dst[i] = src[i] * 45.25483399593904f;
}

__global__ void rms_kernel(const float* __restrict__ x, const float* __restrict__ w,
                           float* __restrict__ out, int cols) {
    __shared__ float red[32];
    size_t base = (size_t)blockIdx.x * cols;
    float ss = 0.f;
    for (int i = threadIdx.x; i < cols; i += blockDim.x) { float v = x[base+i]; ss += v*v; }
    ss = block_reduce_sum(ss, red);
    float inv = rsqrtf(ss / (float)cols + EPS_);
    for (int i = threadIdx.x; i < cols; i += blockDim.x) {
        float v = x[base+i] * inv;
        if (w) v *= w[i];
        out[base+i] = v;
    }
}

// rms(x,w) -> bf16 hi/lo split directly (gemm A input)
__global__ void rms_split_kernel(const float* __restrict__ x, const float* __restrict__ w,
                                 __nv_bfloat16* __restrict__ hi,
                                 __nv_bfloat16* __restrict__ lo) {
    __shared__ float red[32];
    size_t base = (size_t)blockIdx.x * HH;
    float ss = 0.f;
    for (int i = threadIdx.x; i < HH; i += blockDim.x) { float v = x[base+i]; ss += v*v; }
    ss = block_reduce_sum(ss, red);
    float inv = rsqrtf(ss / (float)HH + EPS_);
    for (int i = threadIdx.x; i < HH; i += blockDim.x) {
        float v = x[base+i] * inv * w[i];
        __nv_bfloat16 h, l;
        split1(v, h, l);
        hi[base+i] = h;
        lo[base+i] = l;
    }
}

__global__ void add_rms_kernel(float* __restrict__ h, const float* __restrict__ x,
                               const float* __restrict__ w, int cols) {
    __shared__ float red[32];
    size_t base = (size_t)blockIdx.x * cols;
    float ss = 0.f;
    for (int i = threadIdx.x; i < cols; i += blockDim.x) { float v = x[base+i]; ss += v*v; }
    ss = block_reduce_sum(ss, red);
    float inv = rsqrtf(ss / (float)cols + EPS_);
    for (int i = threadIdx.x; i < cols; i += blockDim.x)
        h[base+i] += x[base+i] * inv * w[i];
}

__global__ void rope_norm_kernel(float* __restrict__ x, const float* __restrict__ nw,
                                 int nheads, float theta) {
    __shared__ float red[32];
    __shared__ float sn[DD];
    int t = blockIdx.x, hd = blockIdx.y, d = threadIdx.x;
    size_t base = ((size_t)t * nheads + hd) * DD;
    float v = x[base + d];
    float ss = block_reduce_sum(v * v, red);
    float n = v * rsqrtf(ss * (1.f / (float)DD) + EPS_) * nw[d];
    sn[d] = n;
    int j = d & 127;
    float invf = (float)exp(-((double)j / 128.0) * log((double)theta));
    float ang = (float)t * invf;
    float c = (float)cos((double)ang);
    float s = (float)sin((double)ang);
    __syncthreads();
    float other = (d < 128) ? -sn[d + 128] : sn[d - 128];
    x[base + d] = n * c + other * s;
}

// gelu(gate)*up -> bf16 hi/lo split directly
__global__ void gelu_mul_split_kernel(const float4* __restrict__ g,
                                      const float4* __restrict__ u,
                                      __nv_bfloat162* __restrict__ hi,
                                      __nv_bfloat162* __restrict__ lo, size_t n4) {
    size_t i = (size_t)blockIdx.x * blockDim.x + threadIdx.x;
    if (i >= n4) return;
    float4 gv = g[i], uv = u[i];
    float r[4];
    float gg[4] = {gv.x, gv.y, gv.z, gv.w};
    float uu[4] = {uv.x, uv.y, uv.z, uv.w};
    #pragma unroll
    for (int q = 0; q < 4; q++) {
        float xv = gg[q];
        float tt = tanhf(0.7978845608028654f * (xv + 0.044715f * xv * xv * xv));
        r[q] = 0.5f * xv * (1.f + tt) * uu[q];
    }
    __nv_bfloat16 h[4], l[4];
    #pragma unroll
    for (int q = 0; q < 4; q++) split1(r[q], h[q], l[q]);
    hi[2*i]   = __nv_bfloat162(h[0], h[1]);
    hi[2*i+1] = __nv_bfloat162(h[2], h[3]);
    lo[2*i]   = __nv_bfloat162(l[0], l[1]);
    lo[2*i+1] = __nv_bfloat162(l[2], l[3]);
}

// ---------------------------------------------------------------------------
// Attention v2: 32 keys/iter, warp0 softmax, float4 paths.
// Output written directly as bf16 hi/lo split (input of o-projection GEMM).
// ---------------------------------------------------------------------------
__global__ void attn_kernel(const float* __restrict__ q, const float* __restrict__ k,
                            const float* __restrict__ v,
                            __nv_bfloat16* __restrict__ oh,
                            __nv_bfloat16* __restrict__ ol, int win) {
    int t = blockIdx.x, hh = blockIdx.y;
    int kv = hh >> 2;
    int tid = threadIdx.x, lane = tid & 31, w = tid >> 5;
    __shared__ float4 sq4[64];
    __shared__ float  sp[32];
    __shared__ float  sscale;
    __shared__ float  slsum;
    __shared__ float4 sred[4][64];

    if (tid < 64)
        sq4[tid] = ((const float4*)(q + ((size_t)t * NHD + hh) * DD))[tid];
    __syncthreads();

    int kq = tid >> 6, dq = tid & 63;
    float4 acc = make_float4(0.f, 0.f, 0.f, 0.f);
    float m = -3.4e38f, l = 0.f;     // live in warp 0
    int slo = 0;
    if (win > 0) { slo = t - win + 1; if (slo < 0) slo = 0; }

    for (int s0 = slo; s0 <= t; s0 += 32) {
        // phase A: scores for 32 keys; warp w keys s0+4w+g, 8 lanes per key
        int g = lane >> 3, sl8 = lane & 7;
        int s = s0 + 4 * w + g;
        float d = 0.f;
        if (s <= t) {
            const float4* kr = (const float4*)(k + ((size_t)s * NKV_ + kv) * DD);
            #pragma unroll
            for (int j = 0; j < 8; j++) {
                float4 kv4 = kr[sl8 + 8 * j];
                float4 q4  = sq4[sl8 + 8 * j];
                d = fmaf(q4.x, kv4.x, fmaf(q4.y, kv4.y,
                    fmaf(q4.z, kv4.z, fmaf(q4.w, kv4.w, d))));
            }
        }
        d += __shfl_xor_sync(0xffffffffu, d, 1);
        d += __shfl_xor_sync(0xffffffffu, d, 2);
        d += __shfl_xor_sync(0xffffffffu, d, 4);
        if (sl8 == 0) sp[4 * w + g] = (s <= t) ? d : -3.4e38f;
        __syncthreads();

        // phase B: warp 0 computes softmax chunk
        if (w == 0) {
            float sc = sp[lane];
            float mn = fmaxf(sc, m);
            #pragma unroll
            for (int off = 16; off; off >>= 1)
                mn = fmaxf(mn, __shfl_xor_sync(0xffffffffu, mn, off));
            float p = expf(sc - mn);
            sp[lane] = p;
            float ps = p;
            #pragma unroll
            for (int off = 16; off; off >>= 1)
                ps += __shfl_xor_sync(0xffffffffu, ps, off);
            float scl = expf(m - mn);
            l = l * scl + ps;
            m = mn;
            if (lane == 0) sscale = scl;
        }
        __syncthreads();

        // phase C: V accumulation, 4-way key split x 64 d-threads
        float scl = sscale;
        acc.x *= scl; acc.y *= scl; acc.z *= scl; acc.w *= scl;
        #pragma unroll
        for (int j8 = 0; j8 < 8; j8++) {
            int jj = kq + 4 * j8;
            int s2 = s0 + jj;
            if (s2 <= t) {
                float p = sp[jj];
                float4 v4 = ((const float4*)(v + ((size_t)s2 * NKV_ + kv) * DD))[dq];
                acc.x = fmaf(p, v4.x, acc.x);
                acc.y = fmaf(p, v4.y, acc.y);
                acc.z = fmaf(p, v4.z, acc.z);
                acc.w = fmaf(p, v4.w, acc.w);
            }
        }
        __syncthreads();   // protect sp for next iteration
    }

    if (tid == 0) slsum = l;
    sred[kq][dq] = acc;
    __syncthreads();
    if (tid < 64) {
        float inv = 1.f / slsum;
        float4 a = sred[0][tid], b = sred[1][tid], c = sred[2][tid], e = sred[3][tid];
        float r0 = (a.x + b.x + c.x + e.x) * inv;
        float r1 = (a.y + b.y + c.y + e.y) * inv;
        float r2 = (a.z + b.z + c.z + e.z) * inv;
        float r3 = (a.w + b.w + c.w + e.w) * inv;
        size_t off = ((size_t)t * NHD + hh) * DD + tid * 4;
        __nv_bfloat16 h0,h1,h2,h3,l0,l1,l2,l3;
        split1(r0,h0,l0); split1(r1,h1,l1); split1(r2,h2,l2); split1(r3,h3,l3);
        ((__nv_bfloat162*)(oh + off))[0] = __nv_bfloat162(h0, h1);
        ((__nv_bfloat162*)(oh + off))[1] = __nv_bfloat162(h2, h3);
        ((__nv_bfloat162*)(ol + off))[0] = __nv_bfloat162(l0, l1);
        ((__nv_bfloat162*)(ol + off))[1] = __nv_bfloat162(l2, l3);
    }
}

// ---------------------------------------------------------------------------
// Host orchestration
// ---------------------------------------------------------------------------
extern "C" void kernel_launch(void* const* d_in, const int* in_sizes, int n_in,
                              void* d_out, int out_size) {
    const float* embed  = (const float*)d_in[0];
    const float* q_w    = (const float*)d_in[1];
    const float* k_w    = (const float*)d_in[2];
    const float* v_w    = (const float*)d_in[3];
    const float* o_w    = (const float*)d_in[4];
    const float* q_norm = (const float*)d_in[5];
    const float* k_norm = (const float*)d_in[6];
    const float* ln1    = (const float*)d_in[7];
    const float* ln2    = (const float*)d_in[8];
    const float* ln3    = (const float*)d_in[9];
    const float* ln4    = (const float*)d_in[10];
    const float* gate_w = (const float*)d_in[11];
    const float* up_w   = (const float*)d_in[12];
    const float* down_w = (const float*)d_in[13];
    const float* fnorm  = (const float*)d_in[14];
    const int*   ids    = (const int*)d_in[15];

    float *h, *q, *k, *v, *tmp, *gate, *up;
    cudaGetSymbolAddress((void**)&h,    g_h);
    cudaGetSymbolAddress((void**)&q,    g_q);
    cudaGetSymbolAddress((void**)&k,    g_k);
    cudaGetSymbolAddress((void**)&v,    g_v);
    cudaGetSymbolAddress((void**)&tmp,  g_tmp);
    cudaGetSymbolAddress((void**)&gate, g_gate);
    cudaGetSymbolAddress((void**)&up,   g_up);

    __nv_bfloat16 *qwh,*qwl,*kwh,*kwl,*vwh,*vwl,*owh,*owl,*gwh,*gwl,*uwh,*uwl,*dwh,*dwl;
    __nv_bfloat16 *xah,*xal,*gah,*gal;
    cudaGetSymbolAddress((void**)&qwh, g_qw_h); cudaGetSymbolAddress((void**)&qwl, g_qw_l);
    cudaGetSymbolAddress((void**)&kwh, g_kw_h); cudaGetSymbolAddress((void**)&kwl, g_kw_l);
    cudaGetSymbolAddress((void**)&vwh, g_vw_h); cudaGetSymbolAddress((void**)&vwl, g_vw_l);
    cudaGetSymbolAddress((void**)&owh, g_ow_h); cudaGetSymbolAddress((void**)&owl, g_ow_l);
    cudaGetSymbolAddress((void**)&gwh, g_gw_h); cudaGetSymbolAddress((void**)&gwl, g_gw_l);
    cudaGetSymbolAddress((void**)&uwh, g_uw_h); cudaGetSymbolAddress((void**)&uwl, g_uw_l);
    cudaGetSymbolAddress((void**)&dwh, g_dw_h); cudaGetSymbolAddress((void**)&dwl, g_dw_l);
    cudaGetSymbolAddress((void**)&xah, g_xa_h); cudaGetSymbolAddress((void**)&xal, g_xa_l);
    cudaGetSymbolAddress((void**)&gah, g_ga_h); cudaGetSymbolAddress((void**)&gal, g_ga_l);

    cudaFuncSetAttribute(gemm_mma, cudaFuncAttributeMaxDynamicSharedMemorySize, GEMM_SMEM);

    // one fused weight-split launch (launch 0)
    WSplit ws;
    size_t nseg[7] = {
        (size_t)L_*HH*HH/4, (size_t)L_*NKV_*DD*HH/4, (size_t)L_*NKV_*DD*HH/4,
        (size_t)L_*HH*HH/4, (size_t)L_*II*HH/4, (size_t)L_*II*HH/4, (size_t)L_*HH*II/4 };
    const float* srcs[7] = {q_w, k_w, v_w, o_w, gate_w, up_w, down_w};
    __nv_bfloat16* his[7] = {qwh, kwh, vwh, owh, gwh, uwh, dwh};
    __nv_bfloat16* los[7] = {qwl, kwl, vwl, owl, gwl, uwl, dwl};
    ws.cum[0] = 0;
    for (int s = 0; s < 7; s++) {
        ws.src[s] = (const float4*)srcs[s];
        ws.hi[s]  = (__nv_bfloat162*)his[s];
        ws.lo[s]  = (__nv_bfloat162*)los[s];
        ws.cum[s+1] = ws.cum[s] + nseg[s];
    }
    wsplit_kernel<<<(unsigned)((ws.cum[7] + 255) / 256), 256>>>(ws);

    embed_kernel<<<TT, 256>>>(embed, ids, h);                 // launch 1

    auto gemm = [&](const __nv_bfloat16* Ah, const __nv_bfloat16* Al,
                    const __nv_bfloat16* Bh, const __nv_bfloat16* Bl,
                    float* C, int M, int N, int K) {
        dim3 grid(N / 128, M / 128);
        gemm_mma<<<grid, 256, GEMM_SMEM>>>(Ah, Al, Bh, Bl, C, M, N, K);
    };

    for (int l = 0; l < 4; l++) {
        bool sliding = (l % 2 == 0);
        float theta  = sliding ? 10000.0f : 1000000.0f;
        int   win    = sliding ? WIN_ : 0;

        // x = rms(h, ln1) -> bf16 split (launch 2 on l==0)
        rms_split_kernel<<<TT, 256>>>(h, ln1 + (size_t)l * HH, xah, xal);

        // k, v first; q at launch index 5 for ncu (-s 5)
        gemm(xah, xal, kwh + (size_t)l*NKV_*DD*HH, kwl + (size_t)l*NKV_*DD*HH, k, TT, NKV_*DD, HH);
        gemm(xah, xal, vwh + (size_t)l*NKV_*DD*HH, vwl + (size_t)l*NKV_*DD*HH, v, TT, NKV_*DD, HH);
        gemm(xah, xal, qwh + (size_t)l*HH*HH,      qwl + (size_t)l*HH*HH,      q, TT, HH,      HH);

        rope_norm_kernel<<<dim3(TT, NHD),  256>>>(q, q_norm + (size_t)l * DD, NHD,  theta);
        rope_norm_kernel<<<dim3(TT, NKV_), 256>>>(k, k_norm + (size_t)l * DD, NKV_, theta);
        rms_kernel<<<TT * NKV_, 256>>>(v, nullptr, v, DD);

        // attention writes bf16 split output directly
        attn_kernel<<<dim3(TT, NHD), 256>>>(q, k, v, xah, xal, win);

        gemm(xah, xal, owh + (size_t)l*HH*HH, owl + (size_t)l*HH*HH, tmp, TT, HH, HH);
        add_rms_kernel<<<TT, 256>>>(h, tmp, ln2 + (size_t)l * HH, HH);

        rms_split_kernel<<<TT, 256>>>(h, ln3 + (size_t)l * HH, xah, xal);
        gemm(xah, xal, gwh + (size_t)l*II*HH, gwl + (size_t)l*II*HH, gate, TT, II, HH);
        gemm(xah, xal, uwh + (size_t)l*II*HH, uwl + (size_t)l*II*HH, up,   TT, II, HH);
        gelu_mul_split_kernel<<<(unsigned)(((size_t)TT*II/4 + 255) / 256), 256>>>(
            (const float4*)gate, (const float4*)up,
            (__nv_bfloat162*)gah, (__nv_bfloat162*)gal, (size_t)TT * II / 4);
        gemm(gah, gal, dwh + (size_t)l*HH*II, dwl + (size_t)l*HH*II, tmp, TT, HH, II);
        add_rms_kernel<<<TT, 256>>>(h, tmp, ln4 + (size_t)l * HH, HH);
    }

    rms_kernel<<<TT, 256>>>(h, fnorm, (float*)d_out, HH);
}

// round 13
// speedup vs baseline: 2.2728x; 1.0292x over previous
#include <cuda_runtime.h>
#include <cuda_bf16.h>
#include <math.h>
#include <stdint.h>

// ---------------------------------------------------------------------------
// Model constants
// ---------------------------------------------------------------------------
#define TT   2048
#define HH   2048
#define NHD  8
#define NKV_ 2
#define DD   256
#define II   8192
#define L_   4
#define WIN_ 512
#define EPS_ 1e-6f

#define QKV_N 3072              // 2048 q + 512 k + 512 v
#define GU_N  16384             // 8192 gate + 8192 up

// ---------------------------------------------------------------------------
// fp32 scratch
// ---------------------------------------------------------------------------
__device__ float g_h  [TT * HH];
__device__ float g_qkv[TT * QKV_N];
__device__ float g_tmp[TT * HH];
__device__ float g_gu [(size_t)TT * GU_N];

// bf16 split (hi/lo) weights, concatenated layouts
__device__ __nv_bfloat16 g_qkvw_h[(size_t)L_*QKV_N*HH], g_qkvw_l[(size_t)L_*QKV_N*HH];
__device__ __nv_bfloat16 g_ow_h  [(size_t)L_*HH*HH],    g_ow_l  [(size_t)L_*HH*HH];
__device__ __nv_bfloat16 g_guw_h [(size_t)L_*GU_N*HH],  g_guw_l [(size_t)L_*GU_N*HH];
__device__ __nv_bfloat16 g_dw_h  [(size_t)L_*HH*II],    g_dw_l  [(size_t)L_*HH*II];
// bf16 split activations
__device__ __nv_bfloat16 g_xa_h[TT*HH],           g_xa_l[TT*HH];
__device__ __nv_bfloat16 g_ga_h[(size_t)TT*II],   g_ga_l[(size_t)TT*II];

// ---------------------------------------------------------------------------
// helpers
// ---------------------------------------------------------------------------
__device__ __forceinline__ uint32_t smem_u32(const void* p) {
    uint32_t a;
    asm("{ .reg .u64 t; cvta.to.shared.u64 t, %1; cvt.u32.u64 %0, t; }" : "=r"(a) : "l"(p));
    return a;
}
__device__ __forceinline__ void cp16(uint32_t dst, const void* src) {
    asm volatile("cp.async.cg.shared.global [%0], [%1], 16;" :: "r"(dst), "l"(src));
}
__device__ __forceinline__ void cp_commit() { asm volatile("cp.async.commit_group;"); }
template<int N> __device__ __forceinline__ void cp_wait() {
    asm volatile("cp.async.wait_group %0;" :: "n"(N));
}
__device__ __forceinline__ void ldsm4(uint32_t* r, uint32_t a) {
    asm volatile("ldmatrix.sync.aligned.m8n8.x4.shared.b16 {%0,%1,%2,%3}, [%4];"
        : "=r"(r[0]), "=r"(r[1]), "=r"(r[2]), "=r"(r[3]) : "r"(a));
}
__device__ __forceinline__ void mma_bf16(float* d, const uint32_t* a, const uint32_t* b) {
    asm volatile("mma.sync.aligned.m16n8k16.row.col.f32.bf16.bf16.f32 "
        "{%0,%1,%2,%3}, {%4,%5,%6,%7}, {%8,%9}, {%0,%1,%2,%3};"
        : "+f"(d[0]), "+f"(d[1]), "+f"(d[2]), "+f"(d[3])
        : "r"(a[0]), "r"(a[1]), "r"(a[2]), "r"(a[3]), "r"(b[0]), "r"(b[1]));
}
__device__ __forceinline__ void split1(float v, __nv_bfloat16& h, __nv_bfloat16& l) {
    h = __float2bfloat16(v);
    l = __float2bfloat16(v - __bfloat162float(h));
}

// ---------------------------------------------------------------------------
// Fused weight split: one launch, 28 segments (per-layer concat targets)
// ---------------------------------------------------------------------------
#define NSEG 28
struct WSplit {
    const float4* src[NSEG];
    __nv_bfloat162* hi[NSEG];
    __nv_bfloat162* lo[NSEG];
    size_t cum[NSEG + 1];       // cumulative float4 counts
};
__global__ void wsplit_kernel(WSplit ws) {
    size_t i = (size_t)blockIdx.x * blockDim.x + threadIdx.x;
    if (i >= ws.cum[NSEG]) return;
    int lo_ = 0, hi_ = NSEG;
    while (hi_ - lo_ > 1) {
        int mid = (lo_ + hi_) >> 1;
        if (i >= ws.cum[mid]) lo_ = mid; else hi_ = mid;
    }
    int seg = lo_;
    size_t j = i - ws.cum[seg];
    float4 v = ws.src[seg][j];
    __nv_bfloat16 h0,h1,h2,h3,l0,l1,l2,l3;
    split1(v.x,h0,l0); split1(v.y,h1,l1); split1(v.z,h2,l2); split1(v.w,h3,l3);
    ws.hi[seg][2*j]   = __nv_bfloat162(h0,h1);
    ws.hi[seg][2*j+1] = __nv_bfloat162(h2,h3);
    ws.lo[seg][2*j]   = __nv_bfloat162(l0,l1);
    ws.lo[seg][2*j+1] = __nv_bfloat162(l2,l3);
}

// ---------------------------------------------------------------------------
// mma.sync bf16-split NT GEMM:  C[M,N] = A[M,K] * B[N,K]^T  (fp32 accuracy)
// 128x128 CTA tile, BK=32, 8 warps, double-buffered, 2 CTAs/SM.
// ---------------------------------------------------------------------------
#define BK_       32
#define STRIDE_E  40
#define ROW_B     (STRIDE_E * 2)            // 80 bytes per row
#define MAT_B     (128 * ROW_B)             // 10240 bytes per matrix tile
#define STAGE_B   (4 * MAT_B)
#define GEMM_SMEM (2 * STAGE_B)             // 81920

__device__ __forceinline__ void gemm_load_stage(
    const __nv_bfloat16* __restrict__ Ah, const __nv_bfloat16* __restrict__ Al,
    const __nv_bfloat16* __restrict__ Bh, const __nv_bfloat16* __restrict__ Bl,
    int K, int bm, int bn, int k0, uint32_t sb, int tid)
{
    #pragma unroll
    for (int i = 0; i < 2; i++) {
        int idx = tid + (i << 8);
        int r = idx >> 2;
        int c = idx & 3;
        size_t ga = (size_t)(bm + r) * K + k0 + c * 8;
        size_t gb = (size_t)(bn + r) * K + k0 + c * 8;
        uint32_t so = r * ROW_B + c * 16;
        cp16(sb           + so, Ah + ga);
        cp16(sb +   MAT_B + so, Al + ga);
        cp16(sb + 2*MAT_B + so, Bh + gb);
        cp16(sb + 3*MAT_B + so, Bl + gb);
    }
    cp_commit();
}

__global__ __launch_bounds__(256, 2)
void gemm_mma(const __nv_bfloat16* __restrict__ Ah, const __nv_bfloat16* __restrict__ Al,
              const __nv_bfloat16* __restrict__ Bh, const __nv_bfloat16* __restrict__ Bl,
              float* __restrict__ C, int M, int N, int K)
{
    extern __shared__ char dsm[];
    uint32_t sbase = smem_u32(dsm);
    int tid  = threadIdx.x;
    int lane = tid & 31, w = tid >> 5;
    int wm = w >> 2, wn = w & 3;
    int bm = blockIdx.y * 128, bn = blockIdx.x * 128;

    float acc[4][4][4];
    #pragma unroll
    for (int i = 0; i < 4; i++)
        #pragma unroll
        for (int j = 0; j < 4; j++)
            #pragma unroll
            for (int q = 0; q < 4; q++) acc[i][j][q] = 0.f;

    int lrow = lane & 15;
    int lkb  = (lane >> 4) << 4;

    int nch = K / BK_;
    gemm_load_stage(Ah, Al, Bh, Bl, K, bm, bn, 0, sbase, tid);

    for (int c = 0; c < nch; c++) {
        uint32_t sb = sbase + (c & 1) * STAGE_B;
        if (c + 1 < nch) {
            gemm_load_stage(Ah, Al, Bh, Bl, K, bm, bn, (c + 1) * BK_,
                            sbase + ((c + 1) & 1) * STAGE_B, tid);
            cp_wait<1>();
        } else {
            cp_wait<0>();
        }
        __syncthreads();

        #pragma unroll
        for (int ks = 0; ks < 2; ks++) {
            uint32_t bh[4][2], bl[4][2];
            #pragma unroll
            for (int np = 0; np < 2; np++) {
                uint32_t bbase = sb + 2 * MAT_B +
                                 (wn * 32 + np * 16 + lrow) * ROW_B + ks * 32 + lkb;
                uint32_t r[4];
                ldsm4(r, bbase);
                bh[np*2][0]   = r[0]; bh[np*2][1]   = r[2];
                bh[np*2+1][0] = r[1]; bh[np*2+1][1] = r[3];
                ldsm4(r, bbase + MAT_B);
                bl[np*2][0]   = r[0]; bl[np*2][1]   = r[2];
                bl[np*2+1][0] = r[1]; bl[np*2+1][1] = r[3];
            }
            uint32_t abase = sb + (wm * 64 + lrow) * ROW_B + ks * 32 + lkb;
            #pragma unroll
            for (int mt = 0; mt < 4; mt++) {
                uint32_t ah[4], al[4];
                ldsm4(ah, abase + mt * 16 * ROW_B);
                ldsm4(al, abase + MAT_B + mt * 16 * ROW_B);
                #pragma unroll
                for (int nt = 0; nt < 4; nt++) {
                    mma_bf16(acc[mt][nt], ah, bh[nt]);
                    mma_bf16(acc[mt][nt], ah, bl[nt]);
                    mma_bf16(acc[mt][nt], al, bh[nt]);
                }
            }
        }
        __syncthreads();
    }

    #pragma unroll
    for (int mt = 0; mt < 4; mt++) {
        int row0 = bm + wm * 64 + mt * 16 + (lane >> 2);
        #pragma unroll
        for (int nt = 0; nt < 4; nt++) {
            int col = bn + wn * 32 + nt * 8 + (lane & 3) * 2;
            *(float2*)&C[(size_t)row0 * N + col] =
                make_float2(acc[mt][nt][0], acc[mt][nt][1]);
            *(float2*)&C[(size_t)(row0 + 8) * N + col] =
                make_float2(acc[mt][nt][2], acc[mt][nt][3]);
        }
    }
}

// ---------------------------------------------------------------------------
// norm / elementwise kernels
// ---------------------------------------------------------------------------
__device__ __forceinline__ float block_reduce_sum(float v, float* red) {
    #pragma unroll
    for (int off = 16; off; off >>= 1) v += __shfl_xor_sync(0xffffffffu, v, off);
    int lane = threadIdx.x & 31, wid = threadIdx.x >> 5;
    if (lane == 0) red[wid] = v;
    __syncthreads();
    int nw = (blockDim.x + 31) >> 5;
    if (wid == 0) {
        float s = (threadIdx.x < nw) ? red[threadIdx.x] : 0.f;
        #pragma unroll
        for (int off = 16; off; off >>= 1) s += __shfl_xor_sync(0xffffffffu, s, off);
        if (lane == 0) red[0] = s;
    }
    __syncthreads();
    return red[0];
}

__global__ void embed_kernel(const float* __restrict__ embed,
                             const int* __restrict__ ids, float* __restrict__ h) {
    int t = blockIdx.x;
    const float* src = embed + (size_t)ids[t] * HH;
    float* dst = h + (size_t)t * HH;
    for (int i = threadIdx.x; i < HH; i += blockDim.x)
        dst[i] = src[i] * 45.25483399593904f;
}

__global__ void rms_kernel(const float* __restrict__ x, const float* __restrict__ w,
                           float* __restrict__ out, int cols) {
    __shared__ float red[32];
    size_t base = (size_t)blockIdx.x * cols;
    float ss = 0.f;
    for (int i = threadIdx.x; i < cols; i += blockDim.x) { float v = x[base+i]; ss += v*v; }
    ss = block_reduce_sum(ss, red);
    float inv = rsqrtf(ss / (float)cols + EPS_);
    for (int i = threadIdx.x; i < cols; i += blockDim.x) {
        float v = x[base+i] * inv;
        if (w) v *= w[i];
        out[base+i] = v;
    }
}

// rms(x,w) -> bf16 hi/lo split directly
__global__ void rms_split_kernel(const float* __restrict__ x, const float* __restrict__ w,
                                 __nv_bfloat16* __restrict__ hi,
                                 __nv_bfloat16* __restrict__ lo) {
    __shared__ float red[32];
    size_t base = (size_t)blockIdx.x * HH;
    float ss = 0.f;
    for (int i = threadIdx.x; i < HH; i += blockDim.x) { float v = x[base+i]; ss += v*v; }
    ss = block_reduce_sum(ss, red);
    float inv = rsqrtf(ss / (float)HH + EPS_);
    for (int i = threadIdx.x; i < HH; i += blockDim.x) {
        float v = x[base+i] * inv * w[i];
        __nv_bfloat16 h, l;
        split1(v, h, l);
        hi[base+i] = h;
        lo[base+i] = l;
    }
}

__global__ void add_rms_kernel(float* __restrict__ h, const float* __restrict__ x,
                               const float* __restrict__ w, int cols) {
    __shared__ float red[32];
    size_t base = (size_t)blockIdx.x * cols;
    float ss = 0.f;
    for (int i = threadIdx.x; i < cols; i += blockDim.x) { float v = x[base+i]; ss += v*v; }
    ss = block_reduce_sum(ss, red);
    float inv = rsqrtf(ss / (float)cols + EPS_);
    for (int i = threadIdx.x; i < cols; i += blockDim.x)
        h[base+i] += x[base+i] * inv * w[i];
}

// h += rms(x)*wa;  then  split(rms(h)*wn) -> hi/lo     (residual + next norm fused)
__global__ void add_rms_split2_kernel(float* __restrict__ h, const float* __restrict__ x,
                                      const float* __restrict__ wa,
                                      const float* __restrict__ wn,
                                      __nv_bfloat16* __restrict__ hi,
                                      __nv_bfloat16* __restrict__ lo) {
    __shared__ float red[32];
    size_t base = (size_t)blockIdx.x * HH;
    float ss = 0.f;
    for (int i = threadIdx.x; i < HH; i += blockDim.x) { float v = x[base+i]; ss += v*v; }
    ss = block_reduce_sum(ss, red);
    float inv = rsqrtf(ss / (float)HH + EPS_);
    float ss2 = 0.f;
    for (int i = threadIdx.x; i < HH; i += blockDim.x) {
        float hv = h[base+i] + x[base+i] * inv * wa[i];
        h[base+i] = hv;
        ss2 += hv * hv;
    }
    __syncthreads();
    ss2 = block_reduce_sum(ss2, red);
    float inv2 = rsqrtf(ss2 / (float)HH + EPS_);
    for (int i = threadIdx.x; i < HH; i += blockDim.x) {
        float v = h[base+i] * inv2 * wn[i];
        __nv_bfloat16 hb, lb;
        split1(v, hb, lb);
        hi[base+i] = hb;
        lo[base+i] = lb;
    }
}

// Fused per-head norm+rope for q (heads 0-7), k (8-9) and rms_noscale for v (10-11).
// Operates in-place on the packed qkv buffer (row stride QKV_N).
__global__ void rope_all_kernel(float* __restrict__ qkv, const float* __restrict__ qn,
                                const float* __restrict__ kn, float theta) {
    __shared__ float red[32];
    __shared__ float sn[DD];
    int t = blockIdx.x, hd = blockIdx.y, d = threadIdx.x;
    float* ptr;
    const float* w;
    bool dorope;
    if (hd < 8)       { ptr = qkv + (size_t)t*QKV_N + hd*DD;              w = qn; dorope = true;  }
    else if (hd < 10) { ptr = qkv + (size_t)t*QKV_N + 2048 + (hd-8)*DD;   w = kn; dorope = true;  }
    else              { ptr = qkv + (size_t)t*QKV_N + 2560 + (hd-10)*DD;  w = 0;  dorope = false; }
    float v = ptr[d];
    float ss = block_reduce_sum(v * v, red);
    float inv = rsqrtf(ss * (1.f / (float)DD) + EPS_);
    if (!dorope) { ptr[d] = v * inv; return; }
    float n = v * inv * w[d];
    sn[d] = n;
    int j = d & 127;
    float invf = (float)exp(-((double)j / 128.0) * log((double)theta));
    float ang = (float)t * invf;
    float c = (float)cos((double)ang);
    float s = (float)sin((double)ang);
    __syncthreads();
    float other = (d < 128) ? -sn[d + 128] : sn[d - 128];
    ptr[d] = n * c + other * s;
}

// gelu(gate)*up from packed gu buffer -> bf16 hi/lo split
__global__ void gelu_mul_split_kernel(const float4* __restrict__ gu,
                                      __nv_bfloat162* __restrict__ hi,
                                      __nv_bfloat162* __restrict__ lo, size_t n4) {
    size_t i = (size_t)blockIdx.x * blockDim.x + threadIdx.x;
    if (i >= n4) return;
    size_t row = i >> 11;             // 2048 float4 of gate per row
    size_t c4  = i & 2047;
    float4 gv = gu[row * 4096 + c4];            // gate cols 0..8191
    float4 uv = gu[row * 4096 + 2048 + c4];     // up   cols 8192..16383
    float r[4];
    float gg[4] = {gv.x, gv.y, gv.z, gv.w};
    float uu[4] = {uv.x, uv.y, uv.z, uv.w};
    #pragma unroll
    for (int q = 0; q < 4; q++) {
        float xv = gg[q];
        float tt = tanhf(0.7978845608028654f * (xv + 0.044715f * xv * xv * xv));
        r[q] = 0.5f * xv * (1.f + tt) * uu[q];
    }
    __nv_bfloat16 h[4], l[4];
    #pragma unroll
    for (int q = 0; q < 4; q++) split1(r[q], h[q], l[q]);
    hi[2*i]   = __nv_bfloat162(h[0], h[1]);
    hi[2*i+1] = __nv_bfloat162(h[2], h[3]);
    lo[2*i]   = __nv_bfloat162(l[0], l[1]);
    lo[2*i+1] = __nv_bfloat162(l[2], l[3]);
}

// ---------------------------------------------------------------------------
// Attention v2 on packed qkv (row stride QKV_N). Output -> bf16 hi/lo split.
// ---------------------------------------------------------------------------
__global__ void attn_kernel(const float* __restrict__ qkv,
                            __nv_bfloat16* __restrict__ oh,
                            __nv_bfloat16* __restrict__ ol, int win) {
    int t = blockIdx.x, hh = blockIdx.y;
    int kv = hh >> 2;
    int tid = threadIdx.x, lane = tid & 31, w = tid >> 5;
    __shared__ float4 sq4[64];
    __shared__ float  sp[32];
    __shared__ float  sscale;
    __shared__ float  slsum;
    __shared__ float4 sred[4][64];

    if (tid < 64)
        sq4[tid] = ((const float4*)(qkv + (size_t)t * QKV_N + hh * DD))[tid];
    __syncthreads();

    int kq = tid >> 6, dq = tid & 63;
    float4 acc = make_float4(0.f, 0.f, 0.f, 0.f);
    float m = -3.4e38f, l = 0.f;     // live in warp 0
    int slo = 0;
    if (win > 0) { slo = t - win + 1; if (slo < 0) slo = 0; }

    for (int s0 = slo; s0 <= t; s0 += 32) {
        int g = lane >> 3, sl8 = lane & 7;
        int s = s0 + 4 * w + g;
        float d = 0.f;
        if (s <= t) {
            const float4* kr = (const float4*)(qkv + (size_t)s * QKV_N + 2048 + kv * DD);
            #pragma unroll
            for (int j = 0; j < 8; j++) {
                float4 kv4 = kr[sl8 + 8 * j];
                float4 q4  = sq4[sl8 + 8 * j];
                d = fmaf(q4.x, kv4.x, fmaf(q4.y, kv4.y,
                    fmaf(q4.z, kv4.z, fmaf(q4.w, kv4.w, d))));
            }
        }
        d += __shfl_xor_sync(0xffffffffu, d, 1);
        d += __shfl_xor_sync(0xffffffffu, d, 2);
        d += __shfl_xor_sync(0xffffffffu, d, 4);
        if (sl8 == 0) sp[4 * w + g] = (s <= t) ? d : -3.4e38f;
        __syncthreads();

        if (w == 0) {
            float sc = sp[lane];
            float mn = fmaxf(sc, m);
            #pragma unroll
            for (int off = 16; off; off >>= 1)
                mn = fmaxf(mn, __shfl_xor_sync(0xffffffffu, mn, off));
            float p = expf(sc - mn);
            sp[lane] = p;
            float ps = p;
            #pragma unroll
            for (int off = 16; off; off >>= 1)
                ps += __shfl_xor_sync(0xffffffffu, ps, off);
            float scl = expf(m - mn);
            l = l * scl + ps;
            m = mn;
            if (lane == 0) sscale = scl;
        }
        __syncthreads();

        float scl = sscale;
        acc.x *= scl; acc.y *= scl; acc.z *= scl; acc.w *= scl;
        #pragma unroll
        for (int j8 = 0; j8 < 8; j8++) {
            int jj = kq + 4 * j8;
            int s2 = s0 + jj;
            if (s2 <= t) {
                float p = sp[jj];
                float4 v4 = ((const float4*)(qkv + (size_t)s2 * QKV_N + 2560 + kv * DD))[dq];
                acc.x = fmaf(p, v4.x, acc.x);
                acc.y = fmaf(p, v4.y, acc.y);
                acc.z = fmaf(p, v4.z, acc.z);
                acc.w = fmaf(p, v4.w, acc.w);
            }
        }
        __syncthreads();
    }

    if (tid == 0) slsum = l;
    sred[kq][dq] = acc;
    __syncthreads();
    if (tid < 64) {
        float inv = 1.f / slsum;
        float4 a = sred[0][tid], b = sred[1][tid], c = sred[2][tid], e = sred[3][tid];
        float r0 = (a.x + b.x + c.x + e.x) * inv;
        float r1 = (a.y + b.y + c.y + e.y) * inv;
        float r2 = (a.z + b.z + c.z + e.z) * inv;
        float r3 = (a.w + b.w + c.w + e.w) * inv;
        size_t off = ((size_t)t * NHD + hh) * DD + tid * 4;
        __nv_bfloat16 h0,h1,h2,h3,l0,l1,l2,l3;
        split1(r0,h0,l0); split1(r1,h1,l1); split1(r2,h2,l2); split1(r3,h3,l3);
        ((__nv_bfloat162*)(oh + off))[0] = __nv_bfloat162(h0, h1);
        ((__nv_bfloat162*)(oh + off))[1] = __nv_bfloat162(h2, h3);
        ((__nv_bfloat162*)(ol + off))[0] = __nv_bfloat162(l0, l1);
        ((__nv_bfloat162*)(ol + off))[1] = __nv_bfloat162(l2, l3);
    }
}

// ---------------------------------------------------------------------------
// Host orchestration
// ---------------------------------------------------------------------------
extern "C" void kernel_launch(void* const* d_in, const int* in_sizes, int n_in,
                              void* d_out, int out_size) {
    const float* embed  = (const float*)d_in[0];
    const float* q_w    = (const float*)d_in[1];
    const float* k_w    = (const float*)d_in[2];
    const float* v_w    = (const float*)d_in[3];
    const float* o_w    = (const float*)d_in[4];
    const float* q_norm = (const float*)d_in[5];
    const float* k_norm = (const float*)d_in[6];
    const float* ln1    = (const float*)d_in[7];
    const float* ln2    = (const float*)d_in[8];
    const float* ln3    = (const float*)d_in[9];
    const float* ln4    = (const float*)d_in[10];
    const float* gate_w = (const float*)d_in[11];
    const float* up_w   = (const float*)d_in[12];
    const float* down_w = (const float*)d_in[13];
    const float* fnorm  = (const float*)d_in[14];
    const int*   ids    = (const int*)d_in[15];

    float *h, *qkv, *tmp, *gu;
    cudaGetSymbolAddress((void**)&h,   g_h);
    cudaGetSymbolAddress((void**)&qkv, g_qkv);
    cudaGetSymbolAddress((void**)&tmp, g_tmp);
    cudaGetSymbolAddress((void**)&gu,  g_gu);

    __nv_bfloat16 *qkvwh,*qkvwl,*owh,*owl,*guwh,*guwl,*dwh,*dwl,*xah,*xal,*gah,*gal;
    cudaGetSymbolAddress((void**)&qkvwh, g_qkvw_h); cudaGetSymbolAddress((void**)&qkvwl, g_qkvw_l);
    cudaGetSymbolAddress((void**)&owh,   g_ow_h);   cudaGetSymbolAddress((void**)&owl,   g_ow_l);
    cudaGetSymbolAddress((void**)&guwh,  g_guw_h);  cudaGetSymbolAddress((void**)&guwl,  g_guw_l);
    cudaGetSymbolAddress((void**)&dwh,   g_dw_h);   cudaGetSymbolAddress((void**)&dwl,   g_dw_l);
    cudaGetSymbolAddress((void**)&xah,   g_xa_h);   cudaGetSymbolAddress((void**)&xal,   g_xa_l);
    cudaGetSymbolAddress((void**)&gah,   g_ga_h);   cudaGetSymbolAddress((void**)&gal,   g_ga_l);

    cudaFuncSetAttribute(gemm_mma, cudaFuncAttributeMaxDynamicSharedMemorySize, GEMM_SMEM);

    // ---- one fused weight-split launch (launch 0), 28 segments ------------
    WSplit ws;
    int sidx = 0;
    ws.cum[0] = 0;
    auto add_seg = [&](const float* src, __nv_bfloat16* hb, size_t hb_off,
                       __nv_bfloat16* lb, size_t lb_off, size_t nelem) {
        ws.src[sidx] = (const float4*)src;
        ws.hi[sidx]  = (__nv_bfloat162*)(hb + hb_off);
        ws.lo[sidx]  = (__nv_bfloat162*)(lb + lb_off);
        ws.cum[sidx+1] = ws.cum[sidx] + nelem / 4;
        sidx++;
    };
    for (int l = 0; l < L_; l++) {
        size_t qkvbase = (size_t)l * QKV_N * HH;
        add_seg(q_w + (size_t)l*2048*HH, qkvwh, qkvbase,              qkvwl, qkvbase,              (size_t)2048*HH);
        add_seg(k_w + (size_t)l*512*HH,  qkvwh, qkvbase + 2048ull*HH, qkvwl, qkvbase + 2048ull*HH, (size_t)512*HH);
        add_seg(v_w + (size_t)l*512*HH,  qkvwh, qkvbase + 2560ull*HH, qkvwl, qkvbase + 2560ull*HH, (size_t)512*HH);
        size_t obase = (size_t)l * HH * HH;
        add_seg(o_w + obase, owh, obase, owl, obase, (size_t)HH*HH);
        size_t gubase = (size_t)l * GU_N * HH;
        add_seg(gate_w + (size_t)l*II*HH, guwh, gubase,               guwl, gubase,               (size_t)II*HH);
        add_seg(up_w   + (size_t)l*II*HH, guwh, gubase + (size_t)II*HH, guwl, gubase + (size_t)II*HH, (size_t)II*HH);
        size_t dbase = (size_t)l * HH * II;
        add_seg(down_w + dbase, dwh, dbase, dwl, dbase, (size_t)HH*II);
    }
    wsplit_kernel<<<(unsigned)((ws.cum[NSEG] + 255) / 256), 256>>>(ws);   // launch 0

    embed_kernel<<<TT, 256>>>(embed, ids, h);                             // launch 1

    auto gemm = [&](const __nv_bfloat16* Ah, const __nv_bfloat16* Al,
                    const __nv_bfloat16* Bh, const __nv_bfloat16* Bl,
                    float* C, int M, int N, int K) {
        dim3 grid(N / 128, M / 128);
        gemm_mma<<<grid, 256, GEMM_SMEM>>>(Ah, Al, Bh, Bl, C, M, N, K);
    };

    // x = rms(h, ln1[0]) -> split (launch 2)
    rms_split_kernel<<<TT, 256>>>(h, ln1, xah, xal);

    for (int l = 0; l < 4; l++) {
        bool sliding = (l % 2 == 0);
        float theta  = sliding ? 10000.0f : 1000000.0f;
        int   win    = sliding ? WIN_ : 0;

        // fused qkv projection (launch 3 on l==0)
        gemm(xah, xal, qkvwh + (size_t)l*QKV_N*HH, qkvwl + (size_t)l*QKV_N*HH,
             qkv, TT, QKV_N, HH);

        // fused q/k rope-norm + v rms (launch 4)
        rope_all_kernel<<<dim3(TT, 12), 256>>>(qkv, q_norm + (size_t)l*DD,
                                               k_norm + (size_t)l*DD, theta);

        // attention (launch 5 on l==0) -> bf16 split output
        attn_kernel<<<dim3(TT, NHD), 256>>>(qkv, xah, xal, win);

        // o-projection + fused residual/norm -> mlp input split
        gemm(xah, xal, owh + (size_t)l*HH*HH, owl + (size_t)l*HH*HH, tmp, TT, HH, HH);
        add_rms_split2_kernel<<<TT, 256>>>(h, tmp, ln2 + (size_t)l*HH,
                                           ln3 + (size_t)l*HH, xah, xal);

        // fused gate+up projection
        gemm(xah, xal, guwh + (size_t)l*GU_N*HH, guwl + (size_t)l*GU_N*HH,
             gu, TT, GU_N, HH);
        gelu_mul_split_kernel<<<(unsigned)(((size_t)TT*II/4 + 255) / 256), 256>>>(
            (const float4*)gu, (__nv_bfloat162*)gah, (__nv_bfloat162*)gal,
            (size_t)TT * II / 4);

        // down projection + residual (+ next layer's ln1 split when applicable)
        gemm(gah, gal, dwh + (size_t)l*HH*II, dwl + (size_t)l*HH*II, tmp, TT, HH, II);
        if (l < 3) {
            add_rms_split2_kernel<<<TT, 256>>>(h, tmp, ln4 + (size_t)l*HH,
                                               ln1 + (size_t)(l+1)*HH, xah, xal);
        } else {
            add_rms_kernel<<<TT, 256>>>(h, tmp, ln4 + (size_t)l*HH, HH);
        }
    }

    rms_kernel<<<TT, 256>>>(h, fnorm, (float*)d_out, HH);
}

// round 14
// speedup vs baseline: 2.3918x; 1.0523x over previous
#include <cuda_runtime.h>
#include <cuda_bf16.h>
#include <math.h>
#include <stdint.h>

// ---------------------------------------------------------------------------
// Model constants
// ---------------------------------------------------------------------------
#define TT   2048
#define HH   2048
#define NHD  8
#define NKV_ 2
#define DD   256
#define II   8192
#define L_   4
#define WIN_ 512
#define EPS_ 1e-6f

#define QKV_N 3072              // 2048 q + 512 k + 512 v
#define GU_N  16384             // 8192 gate + 8192 up

// ---------------------------------------------------------------------------
// fp32 scratch
// ---------------------------------------------------------------------------
__device__ float g_h  [TT * HH];
__device__ float g_qkv[TT * QKV_N];
__device__ float g_tmp[TT * HH];
__device__ float g_gu [(size_t)TT * GU_N];

// bf16 split (hi/lo) weights, concatenated layouts
__device__ __nv_bfloat16 g_qkvw_h[(size_t)L_*QKV_N*HH], g_qkvw_l[(size_t)L_*QKV_N*HH];
__device__ __nv_bfloat16 g_ow_h  [(size_t)L_*HH*HH],    g_ow_l  [(size_t)L_*HH*HH];
__device__ __nv_bfloat16 g_guw_h [(size_t)L_*GU_N*HH],  g_guw_l [(size_t)L_*GU_N*HH];
__device__ __nv_bfloat16 g_dw_h  [(size_t)L_*HH*II],    g_dw_l  [(size_t)L_*HH*II];
// bf16 split activations
__device__ __nv_bfloat16 g_xa_h[TT*HH],           g_xa_l[TT*HH];
__device__ __nv_bfloat16 g_ga_h[(size_t)TT*II],   g_ga_l[(size_t)TT*II];

// ---------------------------------------------------------------------------
// helpers
// ---------------------------------------------------------------------------
__device__ __forceinline__ uint32_t smem_u32(const void* p) {
    uint32_t a;
    asm("{ .reg .u64 t; cvta.to.shared.u64 t, %1; cvt.u32.u64 %0, t; }" : "=r"(a) : "l"(p));
    return a;
}
__device__ __forceinline__ void cp16(uint32_t dst, const void* src) {
    asm volatile("cp.async.cg.shared.global [%0], [%1], 16;" :: "r"(dst), "l"(src));
}
__device__ __forceinline__ void cp_commit() { asm volatile("cp.async.commit_group;"); }
template<int N> __device__ __forceinline__ void cp_wait() {
    asm volatile("cp.async.wait_group %0;" :: "n"(N));
}
__device__ __forceinline__ void ldsm4(uint32_t* r, uint32_t a) {
    asm volatile("ldmatrix.sync.aligned.m8n8.x4.shared.b16 {%0,%1,%2,%3}, [%4];"
        : "=r"(r[0]), "=r"(r[1]), "=r"(r[2]), "=r"(r[3]) : "r"(a));
}
__device__ __forceinline__ void mma_bf16(float* d, const uint32_t* a, const uint32_t* b) {
    asm volatile("mma.sync.aligned.m16n8k16.row.col.f32.bf16.bf16.f32 "
        "{%0,%1,%2,%3}, {%4,%5,%6,%7}, {%8,%9}, {%0,%1,%2,%3};"
        : "+f"(d[0]), "+f"(d[1]), "+f"(d[2]), "+f"(d[3])
        : "r"(a[0]), "r"(a[1]), "r"(a[2]), "r"(a[3]), "r"(b[0]), "r"(b[1]));
}
__device__ __forceinline__ void split1(float v, __nv_bfloat16& h, __nv_bfloat16& l) {
    h = __float2bfloat16(v);
    l = __float2bfloat16(v - __bfloat162float(h));
}

// ---------------------------------------------------------------------------
// Fused weight split: one launch, 28 segments (per-layer concat targets)
// ---------------------------------------------------------------------------
#define NSEG 28
struct WSplit {
    const float4* src[NSEG];
    __nv_bfloat162* hi[NSEG];
    __nv_bfloat162* lo[NSEG];
    size_t cum[NSEG + 1];       // cumulative float4 counts
};
__global__ void wsplit_kernel(WSplit ws) {
    size_t i = (size_t)blockIdx.x * blockDim.x + threadIdx.x;
    if (i >= ws.cum[NSEG]) return;
    int lo_ = 0, hi_ = NSEG;
    while (hi_ - lo_ > 1) {
        int mid = (lo_ + hi_) >> 1;
        if (i >= ws.cum[mid]) lo_ = mid; else hi_ = mid;
    }
    int seg = lo_;
    size_t j = i - ws.cum[seg];
    float4 v = ws.src[seg][j];
    __nv_bfloat16 h0,h1,h2,h3,l0,l1,l2,l3;
    split1(v.x,h0,l0); split1(v.y,h1,l1); split1(v.z,h2,l2); split1(v.w,h3,l3);
    ws.hi[seg][2*j]   = __nv_bfloat162(h0,h1);
    ws.hi[seg][2*j+1] = __nv_bfloat162(h2,h3);
    ws.lo[seg][2*j]   = __nv_bfloat162(l0,l1);
    ws.lo[seg][2*j+1] = __nv_bfloat162(l2,l3);
}

// ---------------------------------------------------------------------------
// mma.sync bf16-split NT GEMM:  C[M,N] = A[M,K] * B[N,K]^T  (fp32 accuracy)
// 128x128 CTA tile, BK=32, 8 warps, double-buffered, 2 CTAs/SM.
// ---------------------------------------------------------------------------
#define BK_       32
#define STRIDE_E  40
#define ROW_B     (STRIDE_E * 2)            // 80 bytes per row
#define MAT_B     (128 * ROW_B)             // 10240 bytes per matrix tile
#define STAGE_B   (4 * MAT_B)
#define GEMM_SMEM (2 * STAGE_B)             // 81920

__device__ __forceinline__ void gemm_load_stage(
    const __nv_bfloat16* __restrict__ Ah, const __nv_bfloat16* __restrict__ Al,
    const __nv_bfloat16* __restrict__ Bh, const __nv_bfloat16* __restrict__ Bl,
    int K, int bm, int bn, int k0, uint32_t sb, int tid)
{
    #pragma unroll
    for (int i = 0; i < 2; i++) {
        int idx = tid + (i << 8);
        int r = idx >> 2;
        int c = idx & 3;
        size_t ga = (size_t)(bm + r) * K + k0 + c * 8;
        size_t gb = (size_t)(bn + r) * K + k0 + c * 8;
        uint32_t so = r * ROW_B + c * 16;
        cp16(sb           + so, Ah + ga);
        cp16(sb +   MAT_B + so, Al + ga);
        cp16(sb + 2*MAT_B + so, Bh + gb);
        cp16(sb + 3*MAT_B + so, Bl + gb);
    }
    cp_commit();
}

__global__ __launch_bounds__(256, 2)
void gemm_mma(const __nv_bfloat16* __restrict__ Ah, const __nv_bfloat16* __restrict__ Al,
              const __nv_bfloat16* __restrict__ Bh, const __nv_bfloat16* __restrict__ Bl,
              float* __restrict__ C, int M, int N, int K)
{
    extern __shared__ char dsm[];
    uint32_t sbase = smem_u32(dsm);
    int tid  = threadIdx.x;
    int lane = tid & 31, w = tid >> 5;
    int wm = w >> 2, wn = w & 3;
    int bm = blockIdx.y * 128, bn = blockIdx.x * 128;

    float acc[4][4][4];
    #pragma unroll
    for (int i = 0; i < 4; i++)
        #pragma unroll
        for (int j = 0; j < 4; j++)
            #pragma unroll
            for (int q = 0; q < 4; q++) acc[i][j][q] = 0.f;

    int lrow = lane & 15;
    int lkb  = (lane >> 4) << 4;

    int nch = K / BK_;
    gemm_load_stage(Ah, Al, Bh, Bl, K, bm, bn, 0, sbase, tid);

    for (int c = 0; c < nch; c++) {
        uint32_t sb = sbase + (c & 1) * STAGE_B;
        if (c + 1 < nch) {
            gemm_load_stage(Ah, Al, Bh, Bl, K, bm, bn, (c + 1) * BK_,
                            sbase + ((c + 1) & 1) * STAGE_B, tid);
            cp_wait<1>();
        } else {
            cp_wait<0>();
        }
        __syncthreads();

        #pragma unroll
        for (int ks = 0; ks < 2; ks++) {
            uint32_t bh[4][2], bl[4][2];
            #pragma unroll
            for (int np = 0; np < 2; np++) {
                uint32_t bbase = sb + 2 * MAT_B +
                                 (wn * 32 + np * 16 + lrow) * ROW_B + ks * 32 + lkb;
                uint32_t r[4];
                ldsm4(r, bbase);
                bh[np*2][0]   = r[0]; bh[np*2][1]   = r[2];
                bh[np*2+1][0] = r[1]; bh[np*2+1][1] = r[3];
                ldsm4(r, bbase + MAT_B);
                bl[np*2][0]   = r[0]; bl[np*2][1]   = r[2];
                bl[np*2+1][0] = r[1]; bl[np*2+1][1] = r[3];
            }
            uint32_t abase = sb + (wm * 64 + lrow) * ROW_B + ks * 32 + lkb;
            #pragma unroll
            for (int mt = 0; mt < 4; mt++) {
                uint32_t ah[4], al[4];
                ldsm4(ah, abase + mt * 16 * ROW_B);
                ldsm4(al, abase + MAT_B + mt * 16 * ROW_B);
                #pragma unroll
                for (int nt = 0; nt < 4; nt++) {
                    mma_bf16(acc[mt][nt], ah, bh[nt]);
                    mma_bf16(acc[mt][nt], ah, bl[nt]);
                    mma_bf16(acc[mt][nt], al, bh[nt]);
                }
            }
        }
        __syncthreads();
    }

    #pragma unroll
    for (int mt = 0; mt < 4; mt++) {
        int row0 = bm + wm * 64 + mt * 16 + (lane >> 2);
        #pragma unroll
        for (int nt = 0; nt < 4; nt++) {
            int col = bn + wn * 32 + nt * 8 + (lane & 3) * 2;
            *(float2*)&C[(size_t)row0 * N + col] =
                make_float2(acc[mt][nt][0], acc[mt][nt][1]);
            *(float2*)&C[(size_t)(row0 + 8) * N + col] =
                make_float2(acc[mt][nt][2], acc[mt][nt][3]);
        }
    }
}

// ---------------------------------------------------------------------------
// norm / elementwise kernels
// ---------------------------------------------------------------------------
__device__ __forceinline__ float block_reduce_sum(float v, float* red) {
    #pragma unroll
    for (int off = 16; off; off >>= 1) v += __shfl_xor_sync(0xffffffffu, v, off);
    int lane = threadIdx.x & 31, wid = threadIdx.x >> 5;
    if (lane == 0) red[wid] = v;
    __syncthreads();
    int nw = (blockDim.x + 31) >> 5;
    if (wid == 0) {
        float s = (threadIdx.x < nw) ? red[threadIdx.x] : 0.f;
        #pragma unroll
        for (int off = 16; off; off >>= 1) s += __shfl_xor_sync(0xffffffffu, s, off);
        if (lane == 0) red[0] = s;
    }
    __syncthreads();
    return red[0];
}

__global__ void embed_kernel(const float* __restrict__ embed,
                             const int* __restrict__ ids, float* __restrict__ h) {
    int t = blockIdx.x;
    const float* src = embed + (size_t)ids[t] * HH;
    float* dst = h + (size_t)t * HH;
    for (int i = threadIdx.x; i < HH; i += blockDim.x)
        dst[i] = src[i] * 45.25483399593904f;
}

__global__ void rms_kernel(const float* __restrict__ x, const float* __restrict__ w,
                           float* __restrict__ out, int cols) {
    __shared__ float red[32];
    size_t base = (size_t)blockIdx.x * cols;
    float ss = 0.f;
    for (int i = threadIdx.x; i < cols; i += blockDim.x) { float v = x[base+i]; ss += v*v; }
    ss = block_reduce_sum(ss, red);
    float inv = rsqrtf(ss / (float)cols + EPS_);
    for (int i = threadIdx.x; i < cols; i += blockDim.x) {
        float v = x[base+i] * inv;
        if (w) v *= w[i];
        out[base+i] = v;
    }
}

// rms(x,w) -> bf16 hi/lo split directly
__global__ void rms_split_kernel(const float* __restrict__ x, const float* __restrict__ w,
                                 __nv_bfloat16* __restrict__ hi,
                                 __nv_bfloat16* __restrict__ lo) {
    __shared__ float red[32];
    size_t base = (size_t)blockIdx.x * HH;
    float ss = 0.f;
    for (int i = threadIdx.x; i < HH; i += blockDim.x) { float v = x[base+i]; ss += v*v; }
    ss = block_reduce_sum(ss, red);
    float inv = rsqrtf(ss / (float)HH + EPS_);
    for (int i = threadIdx.x; i < HH; i += blockDim.x) {
        float v = x[base+i] * inv * w[i];
        __nv_bfloat16 h, l;
        split1(v, h, l);
        hi[base+i] = h;
        lo[base+i] = l;
    }
}

__global__ void add_rms_kernel(float* __restrict__ h, const float* __restrict__ x,
                               const float* __restrict__ w, int cols) {
    __shared__ float red[32];
    size_t base = (size_t)blockIdx.x * cols;
    float ss = 0.f;
    for (int i = threadIdx.x; i < cols; i += blockDim.x) { float v = x[base+i]; ss += v*v; }
    ss = block_reduce_sum(ss, red);
    float inv = rsqrtf(ss / (float)cols + EPS_);
    for (int i = threadIdx.x; i < cols; i += blockDim.x)
        h[base+i] += x[base+i] * inv * w[i];
}

// h += rms(x)*wa;  then  split(rms(h)*wn) -> hi/lo     (residual + next norm fused)
__global__ void add_rms_split2_kernel(float* __restrict__ h, const float* __restrict__ x,
                                      const float* __restrict__ wa,
                                      const float* __restrict__ wn,
                                      __nv_bfloat16* __restrict__ hi,
                                      __nv_bfloat16* __restrict__ lo) {
    __shared__ float red[32];
    size_t base = (size_t)blockIdx.x * HH;
    float ss = 0.f;
    for (int i = threadIdx.x; i < HH; i += blockDim.x) { float v = x[base+i]; ss += v*v; }
    ss = block_reduce_sum(ss, red);
    float inv = rsqrtf(ss / (float)HH + EPS_);
    float ss2 = 0.f;
    for (int i = threadIdx.x; i < HH; i += blockDim.x) {
        float hv = h[base+i] + x[base+i] * inv * wa[i];
        h[base+i] = hv;
        ss2 += hv * hv;
    }
    __syncthreads();
    ss2 = block_reduce_sum(ss2, red);
    float inv2 = rsqrtf(ss2 / (float)HH + EPS_);
    for (int i = threadIdx.x; i < HH; i += blockDim.x) {
        float v = h[base+i] * inv2 * wn[i];
        __nv_bfloat16 hb, lb;
        split1(v, hb, lb);
        hi[base+i] = hb;
        lo[base+i] = lb;
    }
}

// Fused per-head norm+rope for q (heads 0-7), k (8-9) and rms_noscale for v (10-11).
// Operates in-place on the packed qkv buffer (row stride QKV_N).
__global__ void rope_all_kernel(float* __restrict__ qkv, const float* __restrict__ qn,
                                const float* __restrict__ kn, float theta) {
    __shared__ float red[32];
    __shared__ float sn[DD];
    int t = blockIdx.x, hd = blockIdx.y, d = threadIdx.x;
    float* ptr;
    const float* w;
    bool dorope;
    if (hd < 8)       { ptr = qkv + (size_t)t*QKV_N + hd*DD;              w = qn; dorope = true;  }
    else if (hd < 10) { ptr = qkv + (size_t)t*QKV_N + 2048 + (hd-8)*DD;   w = kn; dorope = true;  }
    else              { ptr = qkv + (size_t)t*QKV_N + 2560 + (hd-10)*DD;  w = 0;  dorope = false; }
    float v = ptr[d];
    float ss = block_reduce_sum(v * v, red);
    float inv = rsqrtf(ss * (1.f / (float)DD) + EPS_);
    if (!dorope) { ptr[d] = v * inv; return; }
    float n = v * inv * w[d];
    sn[d] = n;
    int j = d & 127;
    float invf = (float)exp(-((double)j / 128.0) * log((double)theta));
    float ang = (float)t * invf;
    float c = (float)cos((double)ang);
    float s = (float)sin((double)ang);
    __syncthreads();
    float other = (d < 128) ? -sn[d + 128] : sn[d - 128];
    ptr[d] = n * c + other * s;
}

// gelu(gate)*up from packed gu buffer -> bf16 hi/lo split
__global__ void gelu_mul_split_kernel(const float4* __restrict__ gu,
                                      __nv_bfloat162* __restrict__ hi,
                                      __nv_bfloat162* __restrict__ lo, size_t n4) {
    size_t i = (size_t)blockIdx.x * blockDim.x + threadIdx.x;
    if (i >= n4) return;
    size_t row = i >> 11;             // 2048 float4 of gate per row
    size_t c4  = i & 2047;
    float4 gv = gu[row * 4096 + c4];            // gate cols 0..8191
    float4 uv = gu[row * 4096 + 2048 + c4];     // up   cols 8192..16383
    float r[4];
    float gg[4] = {gv.x, gv.y, gv.z, gv.w};
    float uu[4] = {uv.x, uv.y, uv.z, uv.w};
    #pragma unroll
    for (int q = 0; q < 4; q++) {
        float xv = gg[q];
        float tt = tanhf(0.7978845608028654f * (xv + 0.044715f * xv * xv * xv));
        r[q] = 0.5f * xv * (1.f + tt) * uu[q];
    }
    __nv_bfloat16 h[4], l[4];
    #pragma unroll
    for (int q = 0; q < 4; q++) split1(r[q], h[q], l[q]);
    hi[2*i]   = __nv_bfloat162(h[0], h[1]);
    hi[2*i+1] = __nv_bfloat162(h[2], h[3]);
    lo[2*i]   = __nv_bfloat162(l[0], l[1]);
    lo[2*i+1] = __nv_bfloat162(l[2], l[3]);
}

// ---------------------------------------------------------------------------
// Attention v4: block per (t, kv-head), 4 q-heads per block.
//  - q fragments in registers (fixed across chunks)
//  - 32 keys/chunk; warp-per-head score layout, coalesced K
//  - 4 parallel softmax warps, probs double-buffered -> 2 barriers/chunk
//  - V float4 read once, 4 per-head accumulators per thread
// Output written directly as bf16 hi/lo split.
// ---------------------------------------------------------------------------
__global__ __launch_bounds__(256)
void attn_kernel(const float* __restrict__ qkv,
                 __nv_bfloat16* __restrict__ oh,
                 __nv_bfloat16* __restrict__ ol, int win) {
    int t = blockIdx.x, kv = blockIdx.y;
    int tid = threadIdx.x, lane = tid & 31, w = tid >> 5;
    int hd_w = w >> 1, sub = w & 1;        // phase-A: head / key-half of this warp
    int g = lane >> 3, sl8 = lane & 7;     // key-group / lane-in-group
    int kq = tid >> 6, r4 = tid & 63;      // phase-C: key-split / d-float4

    __shared__ float  spr[4][32];          // raw scores
    __shared__ float  spp[2][4][32];       // probabilities (double-buffered)
    __shared__ float  sscale[2][4];
    __shared__ float  sl[4];
    __shared__ float4 sred[4][4][64];      // [head][kq][d4]

    // q fragment in registers (phase A): 8 float4 per thread, fixed for all chunks
    float4 qf[8];
    {
        const float4* qr = (const float4*)(qkv + (size_t)t * QKV_N + (kv * 4 + hd_w) * DD);
        #pragma unroll
        for (int x = 0; x < 8; x++) qf[x] = qr[sl8 + 8 * x];
    }

    float4 acc[4];
    #pragma unroll
    for (int i = 0; i < 4; i++) acc[i] = make_float4(0.f, 0.f, 0.f, 0.f);
    float m = -3.4e38f, l = 0.f;           // softmax state (warps 0..3 own head w)

    int slo = 0;
    if (win > 0) { slo = t - win + 1; if (slo < 0) slo = 0; }

    int par = 0;
    for (int s0 = slo; s0 <= t; s0 += 32, par ^= 1) {
        int nv = t - s0 + 1; if (nv > 32) nv = 32;

        // ---- phase A: scores (warp (hd_w,sub) -> keys sub*16 + p*4 + g) ----
        #pragma unroll
        for (int p = 0; p < 4; p++) {
            int j = sub * 16 + p * 4 + g;
            float d = 0.f;
            if (j < nv) {
                const float4* kr = (const float4*)(qkv + (size_t)(s0 + j) * QKV_N
                                                   + 2048 + kv * DD);
                #pragma unroll
                for (int x = 0; x < 8; x++) {
                    float4 k4 = kr[sl8 + 8 * x];
                    d = fmaf(qf[x].x, k4.x, fmaf(qf[x].y, k4.y,
                        fmaf(qf[x].z, k4.z, fmaf(qf[x].w, k4.w, d))));
                }
            }
            d += __shfl_xor_sync(0xffffffffu, d, 1);
            d += __shfl_xor_sync(0xffffffffu, d, 2);
            d += __shfl_xor_sync(0xffffffffu, d, 4);
            if (sl8 == 0) spr[hd_w][j] = d;
        }
        __syncthreads();

        // ---- phase B: softmax chunk, warps 0..3 (head = w) ----
        if (w < 4) {
            float sc = (lane < nv) ? spr[w][lane] : -3.4e38f;
            float mn = fmaxf(m, sc);
            #pragma unroll
            for (int off = 16; off; off >>= 1)
                mn = fmaxf(mn, __shfl_xor_sync(0xffffffffu, mn, off));
            float p = (lane < nv) ? expf(sc - mn) : 0.f;
            spp[par][w][lane] = p;
            float ps = p;
            #pragma unroll
            for (int off = 16; off; off >>= 1)
                ps += __shfl_xor_sync(0xffffffffu, ps, off);
            float scl = expf(m - mn);
            l = l * scl + ps;
            m = mn;
            if (lane == 0) sscale[par][w] = scl;
        }
        __syncthreads();

        // ---- phase C: V accumulation, 4 heads per thread, V read once ----
        {
            float c0 = sscale[par][0], c1 = sscale[par][1],
                  c2 = sscale[par][2], c3 = sscale[par][3];
            acc[0].x *= c0; acc[0].y *= c0; acc[0].z *= c0; acc[0].w *= c0;
            acc[1].x *= c1; acc[1].y *= c1; acc[1].z *= c1; acc[1].w *= c1;
            acc[2].x *= c2; acc[2].y *= c2; acc[2].z *= c2; acc[2].w *= c2;
            acc[3].x *= c3; acc[3].y *= c3; acc[3].z *= c3; acc[3].w *= c3;
        }
        #pragma unroll
        for (int jj = 0; jj < 8; jj++) {
            int j = kq + 4 * jj;
            if (j < nv) {
                float4 v4 = ((const float4*)(qkv + (size_t)(s0 + j) * QKV_N
                                             + 2560 + kv * DD))[r4];
                #pragma unroll
                for (int hd = 0; hd < 4; hd++) {
                    float p = spp[par][hd][j];
                    acc[hd].x = fmaf(p, v4.x, acc[hd].x);
                    acc[hd].y = fmaf(p, v4.y, acc[hd].y);
                    acc[hd].z = fmaf(p, v4.z, acc[hd].z);
                    acc[hd].w = fmaf(p, v4.w, acc[hd].w);
                }
            }
        }
        // no end-of-chunk barrier needed (spp double-buffered; spr only read
        // in phase B which is barrier-separated from the next phase A)
    }

    if (w < 4 && lane == 0) sl[w] = l;
    #pragma unroll
    for (int hd = 0; hd < 4; hd++) sred[hd][kq][r4] = acc[hd];
    __syncthreads();

    {
        int hd_o = tid >> 6;
        float inv = 1.f / sl[hd_o];
        float4 a = sred[hd_o][0][r4], b = sred[hd_o][1][r4],
               c = sred[hd_o][2][r4], e = sred[hd_o][3][r4];
        float r0 = (a.x + b.x + c.x + e.x) * inv;
        float r1 = (a.y + b.y + c.y + e.y) * inv;
        float r2 = (a.z + b.z + c.z + e.z) * inv;
        float r3 = (a.w + b.w + c.w + e.w) * inv;
        size_t off = ((size_t)t * NHD + kv * 4 + hd_o) * DD + r4 * 4;
        __nv_bfloat16 h0,h1,h2,h3,l0,l1,l2,l3;
        split1(r0,h0,l0); split1(r1,h1,l1); split1(r2,h2,l2); split1(r3,h3,l3);
        ((__nv_bfloat162*)(oh + off))[0] = __nv_bfloat162(h0, h1);
        ((__nv_bfloat162*)(oh + off))[1] = __nv_bfloat162(h2, h3);
        ((__nv_bfloat162*)(ol + off))[0] = __nv_bfloat162(l0, l1);
        ((__nv_bfloat162*)(ol + off))[1] = __nv_bfloat162(l2, l3);
    }
}

// ---------------------------------------------------------------------------
// Host orchestration
// ---------------------------------------------------------------------------
extern "C" void kernel_launch(void* const* d_in, const int* in_sizes, int n_in,
                              void* d_out, int out_size) {
    const float* embed  = (const float*)d_in[0];
    const float* q_w    = (const float*)d_in[1];
    const float* k_w    = (const float*)d_in[2];
    const float* v_w    = (const float*)d_in[3];
    const float* o_w    = (const float*)d_in[4];
    const float* q_norm = (const float*)d_in[5];
    const float* k_norm = (const float*)d_in[6];
    const float* ln1    = (const float*)d_in[7];
    const float* ln2    = (const float*)d_in[8];
    const float* ln3    = (const float*)d_in[9];
    const float* ln4    = (const float*)d_in[10];
    const float* gate_w = (const float*)d_in[11];
    const float* up_w   = (const float*)d_in[12];
    const float* down_w = (const float*)d_in[13];
    const float* fnorm  = (const float*)d_in[14];
    const int*   ids    = (const int*)d_in[15];

    float *h, *qkv, *tmp, *gu;
    cudaGetSymbolAddress((void**)&h,   g_h);
    cudaGetSymbolAddress((void**)&qkv, g_qkv);
    cudaGetSymbolAddress((void**)&tmp, g_tmp);
    cudaGetSymbolAddress((void**)&gu,  g_gu);

    __nv_bfloat16 *qkvwh,*qkvwl,*owh,*owl,*guwh,*guwl,*dwh,*dwl,*xah,*xal,*gah,*gal;
    cudaGetSymbolAddress((void**)&qkvwh, g_qkvw_h); cudaGetSymbolAddress((void**)&qkvwl, g_qkvw_l);
    cudaGetSymbolAddress((void**)&owh,   g_ow_h);   cudaGetSymbolAddress((void**)&owl,   g_ow_l);
    cudaGetSymbolAddress((void**)&guwh,  g_guw_h);  cudaGetSymbolAddress((void**)&guwl,  g_guw_l);
    cudaGetSymbolAddress((void**)&dwh,   g_dw_h);   cudaGetSymbolAddress((void**)&dwl,   g_dw_l);
    cudaGetSymbolAddress((void**)&xah,   g_xa_h);   cudaGetSymbolAddress((void**)&xal,   g_xa_l);
    cudaGetSymbolAddress((void**)&gah,   g_ga_h);   cudaGetSymbolAddress((void**)&gal,   g_ga_l);

    cudaFuncSetAttribute(gemm_mma, cudaFuncAttributeMaxDynamicSharedMemorySize, GEMM_SMEM);

    // ---- one fused weight-split launch (launch 0), 28 segments ------------
    WSplit ws;
    int sidx = 0;
    ws.cum[0] = 0;
    auto add_seg = [&](const float* src, __nv_bfloat16* hb, size_t hb_off,
                       __nv_bfloat16* lb, size_t lb_off, size_t nelem) {
        ws.src[sidx] = (const float4*)src;
        ws.hi[sidx]  = (__nv_bfloat162*)(hb + hb_off);
        ws.lo[sidx]  = (__nv_bfloat162*)(lb + lb_off);
        ws.cum[sidx+1] = ws.cum[sidx] + nelem / 4;
        sidx++;
    };
    for (int l = 0; l < L_; l++) {
        size_t qkvbase = (size_t)l * QKV_N * HH;
        add_seg(q_w + (size_t)l*2048*HH, qkvwh, qkvbase,              qkvwl, qkvbase,              (size_t)2048*HH);
        add_seg(k_w + (size_t)l*512*HH,  qkvwh, qkvbase + 2048ull*HH, qkvwl, qkvbase + 2048ull*HH, (size_t)512*HH);
        add_seg(v_w + (size_t)l*512*HH,  qkvwh, qkvbase + 2560ull*HH, qkvwl, qkvbase + 2560ull*HH, (size_t)512*HH);
        size_t obase = (size_t)l * HH * HH;
        add_seg(o_w + obase, owh, obase, owl, obase, (size_t)HH*HH);
        size_t gubase = (size_t)l * GU_N * HH;
        add_seg(gate_w + (size_t)l*II*HH, guwh, gubase,               guwl, gubase,               (size_t)II*HH);
        add_seg(up_w   + (size_t)l*II*HH, guwh, gubase + (size_t)II*HH, guwl, gubase + (size_t)II*HH, (size_t)II*HH);
        size_t dbase = (size_t)l * HH * II;
        add_seg(down_w + dbase, dwh, dbase, dwl, dbase, (size_t)HH*II);
    }
    wsplit_kernel<<<(unsigned)((ws.cum[NSEG] + 255) / 256), 256>>>(ws);   // launch 0

    embed_kernel<<<TT, 256>>>(embed, ids, h);                             // launch 1

    auto gemm = [&](const __nv_bfloat16* Ah, const __nv_bfloat16* Al,
                    const __nv_bfloat16* Bh, const __nv_bfloat16* Bl,
                    float* C, int M, int N, int K) {
        dim3 grid(N / 128, M / 128);
        gemm_mma<<<grid, 256, GEMM_SMEM>>>(Ah, Al, Bh, Bl, C, M, N, K);
    };

    // x = rms(h, ln1[0]) -> split (launch 2)
    rms_split_kernel<<<TT, 256>>>(h, ln1, xah, xal);

    for (int l = 0; l < 4; l++) {
        bool sliding = (l % 2 == 0);
        float theta  = sliding ? 10000.0f : 1000000.0f;
        int   win    = sliding ? WIN_ : 0;

        // fused qkv projection (launch 3 on l==0)
        gemm(xah, xal, qkvwh + (size_t)l*QKV_N*HH, qkvwl + (size_t)l*QKV_N*HH,
             qkv, TT, QKV_N, HH);

        // fused q/k rope-norm + v rms (launch 4)
        rope_all_kernel<<<dim3(TT, 12), 256>>>(qkv, q_norm + (size_t)l*DD,
                                               k_norm + (size_t)l*DD, theta);

        // attention (launch 5 on l==0) -> bf16 split output
        attn_kernel<<<dim3(TT, NKV_), 256>>>(qkv, xah, xal, win);

        // o-projection + fused residual/norm -> mlp input split
        gemm(xah, xal, owh + (size_t)l*HH*HH, owl + (size_t)l*HH*HH, tmp, TT, HH, HH);
        add_rms_split2_kernel<<<TT, 256>>>(h, tmp, ln2 + (size_t)l*HH,
                                           ln3 + (size_t)l*HH, xah, xal);

        // fused gate+up projection
        gemm(xah, xal, guwh + (size_t)l*GU_N*HH, guwl + (size_t)l*GU_N*HH,
             gu, TT, GU_N, HH);
        gelu_mul_split_kernel<<<(unsigned)(((size_t)TT*II/4 + 255) / 256), 256>>>(
            (const float4*)gu, (__nv_bfloat162*)gah, (__nv_bfloat162*)gal,
            (size_t)TT * II / 4);

        // down projection + residual (+ next layer's ln1 split when applicable)
        gemm(gah, gal, dwh + (size_t)l*HH*II, dwl + (size_t)l*HH*II, tmp, TT, HH, II);
        if (l < 3) {
            add_rms_split2_kernel<<<TT, 256>>>(h, tmp, ln4 + (size_t)l*HH,
                                               ln1 + (size_t)(l+1)*HH, xah, xal);
        } else {
            add_rms_kernel<<<TT, 256>>>(h, tmp, ln4 + (size_t)l*HH, HH);
        }
    }

    rms_kernel<<<TT, 256>>>(h, fnorm, (float*)d_out, HH);
}